// round 3
// baseline (speedup 1.0000x reference)
#include <cuda_runtime.h>
#include <math.h>
#include <float.h>

#define NN 4096
#define FF 320
#define MAXDEG 768

// ---------------- scratch (static __device__ globals; no allocations) ----------------
__device__ float g_Wh[NN * FF];
__device__ float g_org[NN * FF];
__device__ float g_D0[NN * FF];
__device__ float g_D1[NN * FF];
__device__ float g_bA[NN * FF];
__device__ float g_bB[NN * FF];
__device__ float g_cent[NN];
__device__ float g_s1[NN];
__device__ float g_s2[NN];
__device__ float g_sc[NN];
__device__ int g_cols[NN * MAXDEG];
__device__ int g_deg[NN];
__device__ int g_idp[NN];
__device__ int g_p1[NN];
__device__ int g_p2[NN];
__device__ int g_pi1[NN];
__device__ int g_pi2[NN];
__device__ int g_i0[NN];
__device__ int g_i1[NN];

// ---------------- adjacency ELL build + degree centrality (warp per row) ----------------
__global__ void build_adj(const float* __restrict__ A, int* __restrict__ cols,
                          int* __restrict__ deg, float* __restrict__ cent) {
    int warp = (blockIdx.x * blockDim.x + threadIdx.x) >> 5;
    int lane = threadIdx.x & 31;
    if (warp >= NN) return;
    long rowoff = (long)warp * NN;
    float sum = 0.f;
    int base = 0;
    for (int c0 = 0; c0 < NN; c0 += 32) {
        float v = A[rowoff + c0 + lane];
        sum += v;
        unsigned m = __ballot_sync(0xffffffffu, v > 0.f);
        if (v > 0.f) {
            int pos = base + __popc(m & ((1u << lane) - 1u));
            if (pos < MAXDEG) cols[(long)warp * MAXDEG + pos] = c0 + lane;
        }
        base += __popc(m);
    }
    for (int o = 16; o; o >>= 1) sum += __shfl_xor_sync(0xffffffffu, sum, o);
    if (lane == 0) {
        deg[warp] = base < MAXDEG ? base : MAXDEG;
        cent[warp] = sum / (float)(NN - 1);
    }
}

__global__ void iota_k(int* p) {
    int i = blockIdx.x * blockDim.x + threadIdx.x;
    if (i < NN) p[i] = i;
}

// ---------------- GEMM: C = [X1 | X2 | cent*nc] @ W ----------------
// BM=128, BN=64, BK=16, 256 threads, 8x4 register tile, float4 smem loads.
#define BM 128
#define BN 64
#define BK 16
#define BMP (BM + 4)

__global__ __launch_bounds__(256) void gemm_cat(
    const float* __restrict__ X1, int K1,
    const float* __restrict__ X2, int K2,
    int nc, const float* __restrict__ cent,
    const float* __restrict__ W, float* __restrict__ C) {
    __shared__ float As[BK][BMP];
    __shared__ float Bs[BK][BN];
    int tid = threadIdx.x;
    int row0 = blockIdx.y * BM;
    int col0 = blockIdx.x * BN;
    int K12 = K1 + K2;
    int Ktot = K12 + nc;
    int tx = tid & 15, ty = tid >> 4;   // 16x16 thread grid
    float acc[8][4];
#pragma unroll
    for (int i = 0; i < 8; i++)
#pragma unroll
        for (int j = 0; j < 4; j++) acc[i][j] = 0.f;

    for (int k0 = 0; k0 < Ktot; k0 += BK) {
        // A tile: 128 rows x 16 k; consecutive threads read consecutive k (coalesced)
#pragma unroll
        for (int l = 0; l < 8; l++) {
            int idx = tid + l * 256;
            int kk = idx & 15, m = idx >> 4;
            int k = k0 + kk;
            int r = row0 + m;
            float v = 0.f;
            if (k < K1) v = X1[(long)r * K1 + k];
            else if (k < K12) v = X2[(long)r * K2 + (k - K1)];
            else if (k < Ktot) v = cent[r];
            As[kk][m] = v;
        }
        // B tile: 16 k x 64 n; consecutive threads read consecutive n (coalesced)
#pragma unroll
        for (int l = 0; l < 4; l++) {
            int idx = tid + l * 256;
            int n = idx & 63, kk = idx >> 6;
            int k = k0 + kk;
            Bs[kk][n] = (k < Ktot) ? W[(long)k * FF + col0 + n] : 0.f;
        }
        __syncthreads();
#pragma unroll
        for (int kk = 0; kk < BK; kk++) {
            float4 a0 = *(const float4*)&As[kk][ty * 8];
            float4 a1 = *(const float4*)&As[kk][ty * 8 + 4];
            float4 b0 = *(const float4*)&Bs[kk][tx * 4];
            float ra[8] = {a0.x, a0.y, a0.z, a0.w, a1.x, a1.y, a1.z, a1.w};
            float rb[4] = {b0.x, b0.y, b0.z, b0.w};
#pragma unroll
            for (int i = 0; i < 8; i++)
#pragma unroll
                for (int j = 0; j < 4; j++) acc[i][j] = fmaf(ra[i], rb[j], acc[i][j]);
        }
        __syncthreads();
    }
#pragma unroll
    for (int i = 0; i < 8; i++)
#pragma unroll
        for (int j = 0; j < 4; j++)
            C[(long)(row0 + ty * 8 + i) * FF + col0 + tx * 4 + j] = acc[i][j];
}

// ---------------- unpool: out[idx[i]][j] = X[i][j] * sigmoid((X @ W^T)[i][j] + b[j]) ----------------
#define BNP (BN + 4)
__global__ __launch_bounds__(256) void gemm_unpool(
    const float* __restrict__ X, const float* __restrict__ W,
    const float* __restrict__ b, const int* __restrict__ idxArr,
    float* __restrict__ out) {
    __shared__ float As[BK][BMP];
    __shared__ float Bs[BK][BNP];
    int tid = threadIdx.x;
    int row0 = blockIdx.y * BM;
    int col0 = blockIdx.x * BN;
    int tx = tid & 15, ty = tid >> 4;
    float acc[8][4];
#pragma unroll
    for (int i = 0; i < 8; i++)
#pragma unroll
        for (int j = 0; j < 4; j++) acc[i][j] = 0.f;

    for (int k0 = 0; k0 < FF; k0 += BK) {
#pragma unroll
        for (int l = 0; l < 8; l++) {
            int idx = tid + l * 256;
            int kk = idx & 15, m = idx >> 4;
            As[kk][m] = X[(long)(row0 + m) * FF + k0 + kk];
        }
        // W^T: Bs[kk][n] = W[(col0+n)*FF + k0+kk]; consecutive threads -> consecutive kk (coalesced)
#pragma unroll
        for (int l = 0; l < 4; l++) {
            int idx = tid + l * 256;
            int kk = idx & 15, n = idx >> 4;
            Bs[kk][n] = W[(long)(col0 + n) * FF + k0 + kk];
        }
        __syncthreads();
#pragma unroll
        for (int kk = 0; kk < BK; kk++) {
            float4 a0 = *(const float4*)&As[kk][ty * 8];
            float4 a1 = *(const float4*)&As[kk][ty * 8 + 4];
            float4 b0 = *(const float4*)&Bs[kk][tx * 4];
            float ra[8] = {a0.x, a0.y, a0.z, a0.w, a1.x, a1.y, a1.z, a1.w};
            float rb[4] = {b0.x, b0.y, b0.z, b0.w};
#pragma unroll
            for (int i = 0; i < 8; i++)
#pragma unroll
                for (int j = 0; j < 4; j++) acc[i][j] = fmaf(ra[i], rb[j], acc[i][j]);
        }
        __syncthreads();
    }
#pragma unroll
    for (int i = 0; i < 8; i++) {
        int r = row0 + ty * 8 + i;
        int dst = idxArr[r];
#pragma unroll
        for (int j = 0; j < 4; j++) {
            int c = col0 + tx * 4 + j;
            float aw = 1.f / (1.f + expf(-(acc[i][j] + b[c])));
            out[(long)dst * FF + c] = X[(long)r * FF + c] * aw;
        }
    }
}

// ---------------- s1/s2 = Wh @ a-halves (warp per row, fully unrolled for MLP) ----------------
__global__ void compute_s(const float* __restrict__ Wh, const float* __restrict__ a,
                          float* __restrict__ s1, float* __restrict__ s2) {
    int warp = (blockIdx.x * blockDim.x + threadIdx.x) >> 5;
    int lane = threadIdx.x & 31;
    if (warp >= NN) return;
    const float* row = Wh + (long)warp * FF;
    float w[10], a1v[10], a2v[10];
#pragma unroll
    for (int it = 0; it < 10; it++) {
        int t = lane + it * 32;
        w[it] = __ldg(row + t);
        a1v[it] = __ldg(a + t);
        a2v[it] = __ldg(a + FF + t);
    }
    float x1 = 0.f, x2 = 0.f;
#pragma unroll
    for (int it = 0; it < 10; it++) {
        x1 = fmaf(w[it], a1v[it], x1);
        x2 = fmaf(w[it], a2v[it], x2);
    }
    for (int o = 16; o; o >>= 1) {
        x1 += __shfl_down_sync(0xffffffffu, x1, o);
        x2 += __shfl_down_sync(0xffffffffu, x2, o);
    }
    if (lane == 0) { s1[warp] = x1; s2[warp] = x2; }
}

// ---------------- pool scores: sigmoid((X@w + b)/100) (warp per row) ----------------
__global__ void scores_k(const float* __restrict__ X, const float* __restrict__ w,
                         const float* __restrict__ b, float* __restrict__ sc) {
    int warp = (blockIdx.x * blockDim.x + threadIdx.x) >> 5;
    int lane = threadIdx.x & 31;
    if (warp >= NN) return;
    const float* row = X + (long)warp * FF;
    float z = 0.f;
#pragma unroll
    for (int it = 0; it < 10; it++) {
        int t = lane + it * 32;
        z = fmaf(__ldg(row + t), __ldg(w + t), z);
    }
    for (int o = 16; o; o >>= 1) z += __shfl_down_sync(0xffffffffu, z, o);
    if (lane == 0) {
        float v = (z + b[0]) * 0.01f;
        sc[warp] = 1.f / (1.f + expf(-v));
    }
}

// ---------------- stable descending rank (top_k with k=N semantics) ----------------
__global__ void rank_kernel(const float* __restrict__ s, int* __restrict__ idxArr) {
    __shared__ int red[256];
    int i = blockIdx.x;
    int tid = threadIdx.x;
    float si = s[i];
    int cnt = 0;
    for (int j = tid; j < NN; j += 256) {
        float sj = s[j];
        cnt += (sj > si) || (sj == si && j < i);
    }
    red[tid] = cnt;
    __syncthreads();
    for (int st = 128; st > 0; st >>= 1) {
        if (tid < st) red[tid] += red[tid + st];
        __syncthreads();
    }
    if (tid == 0) idxArr[red[0]] = i;
}

// ---------------- apply pool: permute X*value, update perm + inverse ----------------
__global__ void pool_apply(const float* __restrict__ Xold, const float* __restrict__ sc,
                           const int* __restrict__ idxArr, const int* __restrict__ pOld,
                           int* __restrict__ pNew, int* __restrict__ pinvNew,
                           float* __restrict__ Xnew) {
    int r = blockIdx.x;
    int o = idxArr[r];
    if (threadIdx.x == 0) {
        int po = pOld[o];
        pNew[r] = po;
        pinvNew[po] = r;
    }
    float v = sc[o];
    int t = threadIdx.x;
    Xnew[(long)r * FF + t] = Xold[(long)o * FF + t] * v;
}

// ---------------- sparse GAT attention + aggregation (block per row, 320 threads) ----------------
__global__ __launch_bounds__(320) void attn_kernel(
    const float* __restrict__ Wh, const float* __restrict__ s1,
    const float* __restrict__ s2, const int* __restrict__ cols,
    const int* __restrict__ deg, const int* __restrict__ p,
    const int* __restrict__ pinv, const float* __restrict__ resid,
    float* __restrict__ out, int applyElu) {
    __shared__ int nb[MAXDEG];      // stores r*FF
    __shared__ float ev[MAXDEG];
    __shared__ float redw[16];
    int i = blockIdx.x;
    int tid = threadIdx.x;
    int wid = tid >> 5, lane = tid & 31;
    int orig = p[i];
    int d = deg[orig];
    float si = s1[i];
    for (int k = tid; k < d; k += 320) {
        int c = cols[(long)orig * MAXDEG + k];
        int r = pinv[c];
        nb[k] = r * FF;
        float e = si + s2[r];
        ev[k] = e > 0.f ? e : 0.2f * e;   // leaky_relu(0.2)
    }
    __syncthreads();
    // max reduce (warp shuffle + cross-warp)
    float m = -FLT_MAX;
    for (int k = tid; k < d; k += 320) m = fmaxf(m, ev[k]);
    for (int o = 16; o; o >>= 1) m = fmaxf(m, __shfl_xor_sync(0xffffffffu, m, o));
    if (lane == 0) redw[wid] = m;
    __syncthreads();
    if (tid < 32) {
        float v = (tid < 10) ? redw[tid] : -FLT_MAX;
        for (int o = 16; o; o >>= 1) v = fmaxf(v, __shfl_xor_sync(0xffffffffu, v, o));
        if (tid == 0) redw[0] = v;
    }
    __syncthreads();
    m = redw[0];
    // exp & sum
    float ssum = 0.f;
    for (int k = tid; k < d; k += 320) {
        float e = expf(ev[k] - m);
        ev[k] = e;
        ssum += e;
    }
    for (int o = 16; o; o >>= 1) ssum += __shfl_xor_sync(0xffffffffu, ssum, o);
    __syncthreads();   // all ev writes done; all reads of redw[0] done
    if (lane == 0) redw[wid] = ssum;
    __syncthreads();
    if (tid < 32) {
        float v = (tid < 10) ? redw[tid] : 0.f;
        for (int o = 16; o; o >>= 1) v += __shfl_xor_sync(0xffffffffu, v, o);
        if (tid == 0) redw[0] = v;
    }
    __syncthreads();
    float inv = 1.f / redw[0];
    // aggregate: one column per thread
    int j = tid;
    float a0 = 0.f, a1 = 0.f, a2 = 0.f, a3 = 0.f;
    int d4 = d & ~3;
    int k = 0;
    for (; k < d4; k += 4) {
        int o0 = nb[k], o1 = nb[k + 1], o2 = nb[k + 2], o3 = nb[k + 3];
        float e0 = ev[k], e1 = ev[k + 1], e2 = ev[k + 2], e3 = ev[k + 3];
        a0 = fmaf(e0, __ldg(Wh + o0 + j), a0);
        a1 = fmaf(e1, __ldg(Wh + o1 + j), a1);
        a2 = fmaf(e2, __ldg(Wh + o2 + j), a2);
        a3 = fmaf(e3, __ldg(Wh + o3 + j), a3);
    }
    for (; k < d; k++) a0 = fmaf(ev[k], __ldg(Wh + nb[k] + j), a0);
    float acc = (a0 + a1) + (a2 + a3);
    acc *= inv;
    if (applyElu) acc = acc > 0.f ? acc : expm1f(acc);
    if (resid) acc += resid[(long)i * FF + j];
    out[(long)i * FF + j] = acc;
}

// ---------------- host driver ----------------
static void* sym(const void* s) {
    void* p = nullptr;
    cudaGetSymbolAddress(&p, s);
    return p;
}

extern "C" void kernel_launch(void* const* d_in, const int* in_sizes, int n_in,
                              void* d_out, int out_size) {
    const float* A        = (const float*)d_in[0];
    const float* X        = (const float*)d_in[1];
    const float* start_W  = (const float*)d_in[2];
    const float* start_a  = (const float*)d_in[3];
    const float* bottom_W = (const float*)d_in[4];
    const float* bottom_a = (const float*)d_in[5];
    const float* end_W    = (const float*)d_in[6];
    const float* end_a    = (const float*)d_in[7];
    const float* down_W0  = (const float*)d_in[8];
    const float* down_a0  = (const float*)d_in[9];
    const float* up_W0    = (const float*)d_in[10];
    const float* up_a0    = (const float*)d_in[11];
    const float* pool_w0  = (const float*)d_in[12];
    const float* pool_b0  = (const float*)d_in[13];
    const float* unpool_w0= (const float*)d_in[14];
    const float* unpool_b0= (const float*)d_in[15];
    const float* down_W1  = (const float*)d_in[16];
    const float* down_a1  = (const float*)d_in[17];
    const float* up_W1    = (const float*)d_in[18];
    const float* up_a1    = (const float*)d_in[19];
    const float* pool_w1  = (const float*)d_in[20];
    const float* pool_b1  = (const float*)d_in[21];
    const float* unpool_w1= (const float*)d_in[22];
    const float* unpool_b1= (const float*)d_in[23];

    float* Wh   = (float*)sym(g_Wh);
    float* org  = (float*)sym(g_org);
    float* D0   = (float*)sym(g_D0);
    float* D1   = (float*)sym(g_D1);
    float* bA   = (float*)sym(g_bA);
    float* bB   = (float*)sym(g_bB);
    float* cent = (float*)sym(g_cent);
    float* s1   = (float*)sym(g_s1);
    float* s2   = (float*)sym(g_s2);
    float* sc   = (float*)sym(g_sc);
    int* cols = (int*)sym(g_cols);
    int* deg  = (int*)sym(g_deg);
    int* idp  = (int*)sym(g_idp);
    int* p1   = (int*)sym(g_p1);
    int* p2   = (int*)sym(g_p2);
    int* pi1  = (int*)sym(g_pi1);
    int* pi2  = (int*)sym(g_pi2);
    int* i0   = (int*)sym(g_i0);
    int* i1   = (int*)sym(g_i1);

    float* outX = (float*)d_out;

    dim3 gemmGrid(FF / BN, NN / BM);   // (5, 32)

    // adjacency + centrality + identity perm
    build_adj<<<NN / 8, 256>>>(A, cols, deg, cent);
    iota_k<<<NN / 256, 256>>>(idp);

    // start GAT: [X | cent | cent] @ start_W -> org (elu)
    gemm_cat<<<gemmGrid, 256>>>(X, FF, nullptr, 0, 2, cent, start_W, Wh);
    compute_s<<<NN / 8, 256>>>(Wh, start_a, s1, s2);
    attn_kernel<<<NN, 320>>>(Wh, s1, s2, cols, deg, idp, idp, nullptr, org, 1);

    // down0 GAT (level 0) -> D0
    gemm_cat<<<gemmGrid, 256>>>(org, FF, nullptr, 0, 1, cent, down_W0, Wh);
    compute_s<<<NN / 8, 256>>>(Wh, down_a0, s1, s2);
    attn_kernel<<<NN, 320>>>(Wh, s1, s2, cols, deg, idp, idp, nullptr, D0, 1);

    // pool 0
    scores_k<<<NN / 8, 256>>>(D0, pool_w0, pool_b0, sc);
    rank_kernel<<<NN, 256>>>(sc, i0);
    pool_apply<<<NN, 320>>>(D0, sc, i0, idp, p1, pi1, bA);

    // down1 GAT (level 1, perm p1) -> D1
    gemm_cat<<<gemmGrid, 256>>>(bA, FF, nullptr, 0, 1, cent, down_W1, Wh);
    compute_s<<<NN / 8, 256>>>(Wh, down_a1, s1, s2);
    attn_kernel<<<NN, 320>>>(Wh, s1, s2, cols, deg, p1, pi1, nullptr, D1, 1);

    // pool 1
    scores_k<<<NN / 8, 256>>>(D1, pool_w1, pool_b1, sc);
    rank_kernel<<<NN, 256>>>(sc, i1);
    pool_apply<<<NN, 320>>>(D1, sc, i1, p1, p2, pi2, bA);

    // bottom GAT (level 2, perm p2) -> bB
    gemm_cat<<<gemmGrid, 256>>>(bA, FF, nullptr, 0, 1, cent, bottom_W, Wh);
    compute_s<<<NN / 8, 256>>>(Wh, bottom_a, s1, s2);
    attn_kernel<<<NN, 320>>>(Wh, s1, s2, cols, deg, p2, pi2, nullptr, bB, 1);

    // unpool 0 (scatter via i1 -> level 1)
    gemm_unpool<<<gemmGrid, 256>>>(bB, unpool_w0, unpool_b0, i1, bA);

    // up0 GAT (level 1, perm p1) -> bB (+D1 residual fused)
    gemm_cat<<<gemmGrid, 256>>>(bA, FF, nullptr, 0, 1, cent, up_W0, Wh);
    compute_s<<<NN / 8, 256>>>(Wh, up_a0, s1, s2);
    attn_kernel<<<NN, 320>>>(Wh, s1, s2, cols, deg, p1, pi1, D1, bB, 1);

    // unpool 1 (scatter via i0 -> level 0)
    gemm_unpool<<<gemmGrid, 256>>>(bB, unpool_w1, unpool_b1, i0, bA);

    // up1 GAT (level 0, identity perm) -> bB (+D0 residual fused)
    gemm_cat<<<gemmGrid, 256>>>(bA, FF, nullptr, 0, 1, cent, up_W1, Wh);
    compute_s<<<NN / 8, 256>>>(Wh, up_a1, s1, s2);
    attn_kernel<<<NN, 320>>>(Wh, s1, s2, cols, deg, idp, idp, D0, bB, 1);

    // end GAT: [bB | org | cent] @ end_W (concat fused into loader), no elu -> d_out
    gemm_cat<<<gemmGrid, 256>>>(bB, FF, org, FF, 1, cent, end_W, Wh);
    compute_s<<<NN / 8, 256>>>(Wh, end_a, s1, s2);
    attn_kernel<<<NN, 320>>>(Wh, s1, s2, cols, deg, idp, idp, nullptr, outX, 0);

    // second output: start_out (== org)
    cudaMemcpyAsync(outX + (long)NN * FF, org, (long)NN * FF * sizeof(float),
                    cudaMemcpyDeviceToDevice);
}

// round 4
// speedup vs baseline: 1.6281x; 1.6281x over previous
#include <cuda_runtime.h>
#include <cuda_fp16.h>
#include <math.h>
#include <float.h>

#define NN 4096
#define FF 320
#define FH 160          // FF/2 (half2 columns)
#define MAXDEG 768

// ---------------- scratch (static __device__ globals; no allocations) ----------------
__device__ float g_Wh[NN * FF];
__device__ __half g_WhH[NN * FF];
__device__ float g_org[NN * FF];
__device__ float g_D0[NN * FF];
__device__ float g_D1[NN * FF];
__device__ float g_bA[NN * FF];
__device__ float g_bB[NN * FF];
__device__ float g_cent[NN];
__device__ float g_s1[NN];
__device__ float g_s2[NN];
__device__ float g_sc[NN];
__device__ int g_cols[NN * MAXDEG];
__device__ int g_deg[NN];
__device__ int g_idp[NN];
__device__ int g_p1[NN];
__device__ int g_p2[NN];
__device__ int g_pi1[NN];
__device__ int g_pi2[NN];
__device__ int g_i0[NN];
__device__ int g_i1[NN];

// ---------------- adjacency ELL build + degree centrality (warp per row) ----------------
__global__ void build_adj(const float* __restrict__ A, int* __restrict__ cols,
                          int* __restrict__ deg, float* __restrict__ cent) {
    int warp = (blockIdx.x * blockDim.x + threadIdx.x) >> 5;
    int lane = threadIdx.x & 31;
    if (warp >= NN) return;
    long rowoff = (long)warp * NN;
    float sum = 0.f;
    int base = 0;
    for (int c0 = 0; c0 < NN; c0 += 32) {
        float v = A[rowoff + c0 + lane];
        sum += v;
        unsigned m = __ballot_sync(0xffffffffu, v > 0.f);
        if (v > 0.f) {
            int pos = base + __popc(m & ((1u << lane) - 1u));
            if (pos < MAXDEG) cols[(long)warp * MAXDEG + pos] = c0 + lane;
        }
        base += __popc(m);
    }
    for (int o = 16; o; o >>= 1) sum += __shfl_xor_sync(0xffffffffu, sum, o);
    if (lane == 0) {
        deg[warp] = base < MAXDEG ? base : MAXDEG;
        cent[warp] = sum / (float)(NN - 1);
    }
}

__global__ void iota_k(int* p) {
    int i = blockIdx.x * blockDim.x + threadIdx.x;
    if (i < NN) p[i] = i;
}

// ---------------- GEMM: C = [X1 | X2 | cent*nc] @ W ; also emits half copy CH ----------------
// BM=64, BN=64, BK=16, 128 threads, 8x4 register tile -> 320 blocks (good SM packing)
#define BM 64
#define BN 64
#define BK 16
#define BMP (BM + 4)

__global__ __launch_bounds__(128) void gemm_cat(
    const float* __restrict__ X1, int K1,
    const float* __restrict__ X2, int K2,
    int nc, const float* __restrict__ cent,
    const float* __restrict__ W, float* __restrict__ C,
    __half* __restrict__ CH) {
    __shared__ float As[BK][BMP];
    __shared__ float Bs[BK][BN];
    int tid = threadIdx.x;
    int row0 = blockIdx.y * BM;
    int col0 = blockIdx.x * BN;
    int K12 = K1 + K2;
    int Ktot = K12 + nc;
    int tx = tid & 15, ty = tid >> 4;   // 16 x 8 thread grid
    float acc[8][4];
#pragma unroll
    for (int i = 0; i < 8; i++)
#pragma unroll
        for (int j = 0; j < 4; j++) acc[i][j] = 0.f;

    for (int k0 = 0; k0 < Ktot; k0 += BK) {
        // A tile: 64 rows x 16 k; consecutive threads read consecutive k
#pragma unroll
        for (int l = 0; l < 8; l++) {
            int idx = tid + l * 128;
            int kk = idx & 15, m = idx >> 4;
            int k = k0 + kk;
            int r = row0 + m;
            float v = 0.f;
            if (k < K1) v = X1[(long)r * K1 + k];
            else if (k < K12) v = X2[(long)r * K2 + (k - K1)];
            else if (k < Ktot) v = cent[r];
            As[kk][m] = v;
        }
        // B tile: 16 k x 64 n; consecutive threads read consecutive n
#pragma unroll
        for (int l = 0; l < 8; l++) {
            int idx = tid + l * 128;
            int n = idx & 63, kk = idx >> 6;
            int k = k0 + kk;
            Bs[kk][n] = (k < Ktot) ? W[(long)k * FF + col0 + n] : 0.f;
        }
        __syncthreads();
#pragma unroll
        for (int kk = 0; kk < BK; kk++) {
            float4 a0 = *(const float4*)&As[kk][ty * 8];
            float4 a1 = *(const float4*)&As[kk][ty * 8 + 4];
            float4 b0 = *(const float4*)&Bs[kk][tx * 4];
            float ra[8] = {a0.x, a0.y, a0.z, a0.w, a1.x, a1.y, a1.z, a1.w};
            float rb[4] = {b0.x, b0.y, b0.z, b0.w};
#pragma unroll
            for (int i = 0; i < 8; i++)
#pragma unroll
                for (int j = 0; j < 4; j++) acc[i][j] = fmaf(ra[i], rb[j], acc[i][j]);
        }
        __syncthreads();
    }
#pragma unroll
    for (int i = 0; i < 8; i++) {
        int r = row0 + ty * 8 + i;
        long base = (long)r * FF + col0 + tx * 4;
#pragma unroll
        for (int j = 0; j < 4; j++) C[base + j] = acc[i][j];
        __half2* hdst = (__half2*)(CH + base);
        hdst[0] = __floats2half2_rn(acc[i][0], acc[i][1]);
        hdst[1] = __floats2half2_rn(acc[i][2], acc[i][3]);
    }
}

// ---------------- unpool: out[idx[i]][j] = X[i][j] * sigmoid((X @ W^T)[i][j] + b[j]) ----------------
#define BNP (BN + 4)
__global__ __launch_bounds__(128) void gemm_unpool(
    const float* __restrict__ X, const float* __restrict__ W,
    const float* __restrict__ b, const int* __restrict__ idxArr,
    float* __restrict__ out) {
    __shared__ float As[BK][BMP];
    __shared__ float Bs[BK][BNP];
    int tid = threadIdx.x;
    int row0 = blockIdx.y * BM;
    int col0 = blockIdx.x * BN;
    int tx = tid & 15, ty = tid >> 4;
    float acc[8][4];
#pragma unroll
    for (int i = 0; i < 8; i++)
#pragma unroll
        for (int j = 0; j < 4; j++) acc[i][j] = 0.f;

    for (int k0 = 0; k0 < FF; k0 += BK) {
#pragma unroll
        for (int l = 0; l < 8; l++) {
            int idx = tid + l * 128;
            int kk = idx & 15, m = idx >> 4;
            As[kk][m] = X[(long)(row0 + m) * FF + k0 + kk];
        }
        // W^T: consecutive threads -> consecutive kk (coalesced)
#pragma unroll
        for (int l = 0; l < 8; l++) {
            int idx = tid + l * 128;
            int kk = idx & 15, n = idx >> 4;
            Bs[kk][n] = W[(long)(col0 + n) * FF + k0 + kk];
        }
        __syncthreads();
#pragma unroll
        for (int kk = 0; kk < BK; kk++) {
            float4 a0 = *(const float4*)&As[kk][ty * 8];
            float4 a1 = *(const float4*)&As[kk][ty * 8 + 4];
            float4 b0 = *(const float4*)&Bs[kk][tx * 4];
            float ra[8] = {a0.x, a0.y, a0.z, a0.w, a1.x, a1.y, a1.z, a1.w};
            float rb[4] = {b0.x, b0.y, b0.z, b0.w};
#pragma unroll
            for (int i = 0; i < 8; i++)
#pragma unroll
                for (int j = 0; j < 4; j++) acc[i][j] = fmaf(ra[i], rb[j], acc[i][j]);
        }
        __syncthreads();
    }
#pragma unroll
    for (int i = 0; i < 8; i++) {
        int r = row0 + ty * 8 + i;
        int dst = idxArr[r];
#pragma unroll
        for (int j = 0; j < 4; j++) {
            int c = col0 + tx * 4 + j;
            float aw = 1.f / (1.f + expf(-(acc[i][j] + b[c])));
            out[(long)dst * FF + c] = X[(long)r * FF + c] * aw;
        }
    }
}

// ---------------- s1/s2 = Wh @ a-halves (warp per row, fully unrolled for MLP) ----------------
__global__ void compute_s(const float* __restrict__ Wh, const float* __restrict__ a,
                          float* __restrict__ s1, float* __restrict__ s2) {
    int warp = (blockIdx.x * blockDim.x + threadIdx.x) >> 5;
    int lane = threadIdx.x & 31;
    if (warp >= NN) return;
    const float* row = Wh + (long)warp * FF;
    float w[10], a1v[10], a2v[10];
#pragma unroll
    for (int it = 0; it < 10; it++) {
        int t = lane + it * 32;
        w[it] = __ldg(row + t);
        a1v[it] = __ldg(a + t);
        a2v[it] = __ldg(a + FF + t);
    }
    float x1 = 0.f, x2 = 0.f;
#pragma unroll
    for (int it = 0; it < 10; it++) {
        x1 = fmaf(w[it], a1v[it], x1);
        x2 = fmaf(w[it], a2v[it], x2);
    }
    for (int o = 16; o; o >>= 1) {
        x1 += __shfl_down_sync(0xffffffffu, x1, o);
        x2 += __shfl_down_sync(0xffffffffu, x2, o);
    }
    if (lane == 0) { s1[warp] = x1; s2[warp] = x2; }
}

// ---------------- pool scores: sigmoid((X@w + b)/100) (warp per row) ----------------
__global__ void scores_k(const float* __restrict__ X, const float* __restrict__ w,
                         const float* __restrict__ b, float* __restrict__ sc) {
    int warp = (blockIdx.x * blockDim.x + threadIdx.x) >> 5;
    int lane = threadIdx.x & 31;
    if (warp >= NN) return;
    const float* row = X + (long)warp * FF;
    float z = 0.f;
#pragma unroll
    for (int it = 0; it < 10; it++) {
        int t = lane + it * 32;
        z = fmaf(__ldg(row + t), __ldg(w + t), z);
    }
    for (int o = 16; o; o >>= 1) z += __shfl_down_sync(0xffffffffu, z, o);
    if (lane == 0) {
        float v = (z + b[0]) * 0.01f;
        sc[warp] = 1.f / (1.f + expf(-v));
    }
}

// ---------------- stable descending rank (top_k with k=N semantics) ----------------
__global__ void rank_kernel(const float* __restrict__ s, int* __restrict__ idxArr) {
    __shared__ int red[256];
    int i = blockIdx.x;
    int tid = threadIdx.x;
    float si = s[i];
    int cnt = 0;
    for (int j = tid; j < NN; j += 256) {
        float sj = s[j];
        cnt += (sj > si) || (sj == si && j < i);
    }
    red[tid] = cnt;
    __syncthreads();
    for (int st = 128; st > 0; st >>= 1) {
        if (tid < st) red[tid] += red[tid + st];
        __syncthreads();
    }
    if (tid == 0) idxArr[red[0]] = i;
}

// ---------------- apply pool: permute X*value, update perm + inverse ----------------
__global__ void pool_apply(const float* __restrict__ Xold, const float* __restrict__ sc,
                           const int* __restrict__ idxArr, const int* __restrict__ pOld,
                           int* __restrict__ pNew, int* __restrict__ pinvNew,
                           float* __restrict__ Xnew) {
    int r = blockIdx.x;
    int o = idxArr[r];
    if (threadIdx.x == 0) {
        int po = pOld[o];
        pNew[r] = po;
        pinvNew[po] = r;
    }
    float v = sc[o];
    int t = threadIdx.x;
    Xnew[(long)r * FF + t] = Xold[(long)o * FF + t] * v;
}

// ---------------- sparse GAT attention + aggregation (block per row, 160 threads, half2 gathers) ----------------
__global__ __launch_bounds__(160) void attn_kernel(
    const __half2* __restrict__ WhH, const float* __restrict__ s1,
    const float* __restrict__ s2, const int* __restrict__ cols,
    const int* __restrict__ deg, const int* __restrict__ p,
    const int* __restrict__ pinv, const float* __restrict__ resid,
    float* __restrict__ out, int applyElu) {
    __shared__ int nb[MAXDEG];      // stores r*FH (half2 row offset)
    __shared__ float ev[MAXDEG];
    __shared__ float redw[8];
    int i = blockIdx.x;
    int tid = threadIdx.x;
    int wid = tid >> 5, lane = tid & 31;
    int orig = p[i];
    int d = deg[orig];
    float si = s1[i];
    for (int k = tid; k < d; k += 160) {
        int c = cols[(long)orig * MAXDEG + k];
        int r = pinv[c];
        nb[k] = r * FH;
        float e = si + s2[r];
        ev[k] = e > 0.f ? e : 0.2f * e;   // leaky_relu(0.2)
    }
    __syncthreads();
    // max reduce (5 warps)
    float m = -FLT_MAX;
    for (int k = tid; k < d; k += 160) m = fmaxf(m, ev[k]);
    for (int o = 16; o; o >>= 1) m = fmaxf(m, __shfl_xor_sync(0xffffffffu, m, o));
    if (lane == 0) redw[wid] = m;
    __syncthreads();
    if (tid < 32) {
        float v = (tid < 5) ? redw[tid] : -FLT_MAX;
        for (int o = 16; o; o >>= 1) v = fmaxf(v, __shfl_xor_sync(0xffffffffu, v, o));
        if (tid == 0) redw[0] = v;
    }
    __syncthreads();
    m = redw[0];
    // exp & sum
    float ssum = 0.f;
    for (int k = tid; k < d; k += 160) {
        float e = expf(ev[k] - m);
        ev[k] = e;
        ssum += e;
    }
    for (int o = 16; o; o >>= 1) ssum += __shfl_xor_sync(0xffffffffu, ssum, o);
    __syncthreads();
    if (lane == 0) redw[wid] = ssum;
    __syncthreads();
    if (tid < 32) {
        float v = (tid < 5) ? redw[tid] : 0.f;
        for (int o = 16; o; o >>= 1) v += __shfl_xor_sync(0xffffffffu, v, o);
        if (tid == 0) redw[0] = v;
    }
    __syncthreads();
    float inv = 1.f / redw[0];
    // aggregate: one half2 column-pair per thread, fp32 accumulate
    int j = tid;   // 0..159
    float ax0 = 0.f, ay0 = 0.f, ax1 = 0.f, ay1 = 0.f;
    float ax2 = 0.f, ay2 = 0.f, ax3 = 0.f, ay3 = 0.f;
    int d4 = d & ~3;
    int k = 0;
    for (; k < d4; k += 4) {
        int o0 = nb[k], o1 = nb[k + 1], o2 = nb[k + 2], o3 = nb[k + 3];
        float e0 = ev[k], e1 = ev[k + 1], e2 = ev[k + 2], e3 = ev[k + 3];
        float2 f0 = __half22float2(__ldg(WhH + o0 + j));
        float2 f1 = __half22float2(__ldg(WhH + o1 + j));
        float2 f2 = __half22float2(__ldg(WhH + o2 + j));
        float2 f3 = __half22float2(__ldg(WhH + o3 + j));
        ax0 = fmaf(e0, f0.x, ax0); ay0 = fmaf(e0, f0.y, ay0);
        ax1 = fmaf(e1, f1.x, ax1); ay1 = fmaf(e1, f1.y, ay1);
        ax2 = fmaf(e2, f2.x, ax2); ay2 = fmaf(e2, f2.y, ay2);
        ax3 = fmaf(e3, f3.x, ax3); ay3 = fmaf(e3, f3.y, ay3);
    }
    for (; k < d; k++) {
        float2 f = __half22float2(__ldg(WhH + nb[k] + j));
        float e = ev[k];
        ax0 = fmaf(e, f.x, ax0); ay0 = fmaf(e, f.y, ay0);
    }
    float accx = ((ax0 + ax1) + (ax2 + ax3)) * inv;
    float accy = ((ay0 + ay1) + (ay2 + ay3)) * inv;
    if (applyElu) {
        accx = accx > 0.f ? accx : expm1f(accx);
        accy = accy > 0.f ? accy : expm1f(accy);
    }
    long base = (long)i * FF + 2 * j;
    if (resid) {
        accx += resid[base];
        accy += resid[base + 1];
    }
    out[base] = accx;
    out[base + 1] = accy;
}

// ---------------- host driver ----------------
static void* sym(const void* s) {
    void* p = nullptr;
    cudaGetSymbolAddress(&p, s);
    return p;
}

extern "C" void kernel_launch(void* const* d_in, const int* in_sizes, int n_in,
                              void* d_out, int out_size) {
    const float* A        = (const float*)d_in[0];
    const float* X        = (const float*)d_in[1];
    const float* start_W  = (const float*)d_in[2];
    const float* start_a  = (const float*)d_in[3];
    const float* bottom_W = (const float*)d_in[4];
    const float* bottom_a = (const float*)d_in[5];
    const float* end_W    = (const float*)d_in[6];
    const float* end_a    = (const float*)d_in[7];
    const float* down_W0  = (const float*)d_in[8];
    const float* down_a0  = (const float*)d_in[9];
    const float* up_W0    = (const float*)d_in[10];
    const float* up_a0    = (const float*)d_in[11];
    const float* pool_w0  = (const float*)d_in[12];
    const float* pool_b0  = (const float*)d_in[13];
    const float* unpool_w0= (const float*)d_in[14];
    const float* unpool_b0= (const float*)d_in[15];
    const float* down_W1  = (const float*)d_in[16];
    const float* down_a1  = (const float*)d_in[17];
    const float* up_W1    = (const float*)d_in[18];
    const float* up_a1    = (const float*)d_in[19];
    const float* pool_w1  = (const float*)d_in[20];
    const float* pool_b1  = (const float*)d_in[21];
    const float* unpool_w1= (const float*)d_in[22];
    const float* unpool_b1= (const float*)d_in[23];

    float* Wh    = (float*)sym(g_Wh);
    __half* WhH  = (__half*)sym(g_WhH);
    float* org   = (float*)sym(g_org);
    float* D0    = (float*)sym(g_D0);
    float* D1    = (float*)sym(g_D1);
    float* bA    = (float*)sym(g_bA);
    float* bB    = (float*)sym(g_bB);
    float* cent  = (float*)sym(g_cent);
    float* s1    = (float*)sym(g_s1);
    float* s2    = (float*)sym(g_s2);
    float* sc    = (float*)sym(g_sc);
    int* cols = (int*)sym(g_cols);
    int* deg  = (int*)sym(g_deg);
    int* idp  = (int*)sym(g_idp);
    int* p1   = (int*)sym(g_p1);
    int* p2   = (int*)sym(g_p2);
    int* pi1  = (int*)sym(g_pi1);
    int* pi2  = (int*)sym(g_pi2);
    int* i0   = (int*)sym(g_i0);
    int* i1   = (int*)sym(g_i1);

    float* outX = (float*)d_out;
    const __half2* WhH2 = (const __half2*)WhH;

    dim3 gemmGrid(FF / BN, NN / BM);   // (5, 64) = 320 blocks

    // adjacency + centrality + identity perm
    build_adj<<<NN / 8, 256>>>(A, cols, deg, cent);
    iota_k<<<NN / 256, 256>>>(idp);

    // start GAT: [X | cent | cent] @ start_W -> org (elu)
    gemm_cat<<<gemmGrid, 128>>>(X, FF, nullptr, 0, 2, cent, start_W, Wh, WhH);
    compute_s<<<NN / 8, 256>>>(Wh, start_a, s1, s2);
    attn_kernel<<<NN, 160>>>(WhH2, s1, s2, cols, deg, idp, idp, nullptr, org, 1);

    // down0 GAT (level 0) -> D0
    gemm_cat<<<gemmGrid, 128>>>(org, FF, nullptr, 0, 1, cent, down_W0, Wh, WhH);
    compute_s<<<NN / 8, 256>>>(Wh, down_a0, s1, s2);
    attn_kernel<<<NN, 160>>>(WhH2, s1, s2, cols, deg, idp, idp, nullptr, D0, 1);

    // pool 0
    scores_k<<<NN / 8, 256>>>(D0, pool_w0, pool_b0, sc);
    rank_kernel<<<NN, 256>>>(sc, i0);
    pool_apply<<<NN, 320>>>(D0, sc, i0, idp, p1, pi1, bA);

    // down1 GAT (level 1, perm p1) -> D1
    gemm_cat<<<gemmGrid, 128>>>(bA, FF, nullptr, 0, 1, cent, down_W1, Wh, WhH);
    compute_s<<<NN / 8, 256>>>(Wh, down_a1, s1, s2);
    attn_kernel<<<NN, 160>>>(WhH2, s1, s2, cols, deg, p1, pi1, nullptr, D1, 1);

    // pool 1
    scores_k<<<NN / 8, 256>>>(D1, pool_w1, pool_b1, sc);
    rank_kernel<<<NN, 256>>>(sc, i1);
    pool_apply<<<NN, 320>>>(D1, sc, i1, p1, p2, pi2, bA);

    // bottom GAT (level 2, perm p2) -> bB
    gemm_cat<<<gemmGrid, 128>>>(bA, FF, nullptr, 0, 1, cent, bottom_W, Wh, WhH);
    compute_s<<<NN / 8, 256>>>(Wh, bottom_a, s1, s2);
    attn_kernel<<<NN, 160>>>(WhH2, s1, s2, cols, deg, p2, pi2, nullptr, bB, 1);

    // unpool 0 (scatter via i1 -> level 1)
    gemm_unpool<<<gemmGrid, 128>>>(bB, unpool_w0, unpool_b0, i1, bA);

    // up0 GAT (level 1, perm p1) -> bB (+D1 residual fused)
    gemm_cat<<<gemmGrid, 128>>>(bA, FF, nullptr, 0, 1, cent, up_W0, Wh, WhH);
    compute_s<<<NN / 8, 256>>>(Wh, up_a0, s1, s2);
    attn_kernel<<<NN, 160>>>(WhH2, s1, s2, cols, deg, p1, pi1, D1, bB, 1);

    // unpool 1 (scatter via i0 -> level 0)
    gemm_unpool<<<gemmGrid, 128>>>(bB, unpool_w1, unpool_b1, i0, bA);

    // up1 GAT (level 0, identity perm) -> bB (+D0 residual fused)
    gemm_cat<<<gemmGrid, 128>>>(bA, FF, nullptr, 0, 1, cent, up_W1, Wh, WhH);
    compute_s<<<NN / 8, 256>>>(Wh, up_a1, s1, s2);
    attn_kernel<<<NN, 160>>>(WhH2, s1, s2, cols, deg, idp, idp, D0, bB, 1);

    // end GAT: [bB | org | cent] @ end_W (concat fused into loader), no elu -> d_out
    gemm_cat<<<gemmGrid, 128>>>(bB, FF, org, FF, 1, cent, end_W, Wh, WhH);
    compute_s<<<NN / 8, 256>>>(Wh, end_a, s1, s2);
    attn_kernel<<<NN, 160>>>(WhH2, s1, s2, cols, deg, idp, idp, nullptr, outX, 0);

    // second output: start_out (== org)
    cudaMemcpyAsync(outX + (long)NN * FF, org, (long)NN * FF * sizeof(float),
                    cudaMemcpyDeviceToDevice);
}

// round 5
// speedup vs baseline: 1.9310x; 1.1860x over previous
#include <cuda_runtime.h>
#include <cuda_fp16.h>
#include <math.h>
#include <float.h>

#define NN 4096
#define FF 320
#define FH 160          // FF/2 (half2 columns)
#define MAXDEG 768

// ---------------- scratch (static __device__ globals; no allocations) ----------------
__device__ float g_Wh[NN * FF];
__device__ __half g_WhH[NN * FF];
__device__ float g_org[NN * FF];
__device__ float g_D0[NN * FF];
__device__ float g_D1[NN * FF];
__device__ float g_bA[NN * FF];
__device__ float g_bB[NN * FF];
__device__ float g_cent[NN];
__device__ float g_s1[NN];
__device__ float g_s2[NN];
__device__ float g_sc[NN];
__device__ int g_cols[NN * MAXDEG];
__device__ int g_deg[NN];
__device__ int g_idp[NN];
__device__ int g_p1[NN];
__device__ int g_p2[NN];
__device__ int g_pi1[NN];
__device__ int g_pi2[NN];
__device__ int g_i0[NN];
__device__ int g_i1[NN];

// ---------------- adjacency ELL build + degree centrality + identity perm (warp per row) ----------------
__global__ void build_adj(const float* __restrict__ A, int* __restrict__ cols,
                          int* __restrict__ deg, float* __restrict__ cent,
                          int* __restrict__ idp) {
    int warp = (blockIdx.x * blockDim.x + threadIdx.x) >> 5;
    int lane = threadIdx.x & 31;
    if (warp >= NN) return;
    long rowoff = (long)warp * NN;
    float sum = 0.f;
    int base = 0;
    for (int c0 = 0; c0 < NN; c0 += 32) {
        float v = A[rowoff + c0 + lane];
        sum += v;
        unsigned m = __ballot_sync(0xffffffffu, v > 0.f);
        if (v > 0.f) {
            int pos = base + __popc(m & ((1u << lane) - 1u));
            if (pos < MAXDEG) cols[(long)warp * MAXDEG + pos] = c0 + lane;
        }
        base += __popc(m);
    }
    for (int o = 16; o; o >>= 1) sum += __shfl_xor_sync(0xffffffffu, sum, o);
    if (lane == 0) {
        deg[warp] = base < MAXDEG ? base : MAXDEG;
        cent[warp] = sum / (float)(NN - 1);
        idp[warp] = warp;
    }
}

// ---------------- GEMM: C = [X1 | X2 | cent*nc] @ W ; also emits half copy CH ----------------
// BM=64, BN=64, BK=16, 128 threads, 8x4 register tile, double-buffered smem.
#define BM 64
#define BN 64
#define BK 16
#define BMP (BM + 4)

__global__ __launch_bounds__(128) void gemm_cat(
    const float* __restrict__ X1, int K1,
    const float* __restrict__ X2, int K2,
    int nc, const float* __restrict__ cent,
    const float* __restrict__ W, float* __restrict__ C,
    __half* __restrict__ CH) {
    __shared__ float As[2][BK][BMP];
    __shared__ float Bs[2][BK][BN];
    int tid = threadIdx.x;
    int row0 = blockIdx.y * BM;
    int col0 = blockIdx.x * BN;
    int K12 = K1 + K2;
    int Ktot = K12 + nc;
    int nT = (Ktot + BK - 1) / BK;
    int tx = tid & 15, ty = tid >> 4;
    float acc[8][4];
#pragma unroll
    for (int i = 0; i < 8; i++)
#pragma unroll
        for (int j = 0; j < 4; j++) acc[i][j] = 0.f;

    // A-element loader indices (fixed per thread)
    int a_kk = tid & 15, a_m0 = tid >> 4;        // +l*8 rows
    int b_n = tid & 63, b_kk0 = tid >> 6;        // +l*2 kk

    // load tile 0 straight to smem
    {
        int k0 = 0;
#pragma unroll
        for (int l = 0; l < 8; l++) {
            int m = a_m0 + l * 8;
            int k = k0 + a_kk;
            int r = row0 + m;
            float v = 0.f;
            if (k < K1) v = X1[(long)r * K1 + k];
            else if (k < K12) v = X2[(long)r * K2 + (k - K1)];
            else if (k < Ktot) v = cent[r];
            As[0][a_kk][m] = v;
        }
#pragma unroll
        for (int l = 0; l < 8; l++) {
            int kk = b_kk0 + l * 2;
            int k = k0 + kk;
            Bs[0][kk][b_n] = (k < Ktot) ? W[(long)k * FF + col0 + b_n] : 0.f;
        }
    }
    __syncthreads();

    float pa[8], pb[8];
    for (int t = 0; t < nT; t++) {
        int buf = t & 1;
        bool hasNext = (t + 1 < nT);
        if (hasNext) {
            int k0 = (t + 1) * BK;
#pragma unroll
            for (int l = 0; l < 8; l++) {
                int m = a_m0 + l * 8;
                int k = k0 + a_kk;
                int r = row0 + m;
                float v = 0.f;
                if (k < K1) v = X1[(long)r * K1 + k];
                else if (k < K12) v = X2[(long)r * K2 + (k - K1)];
                else if (k < Ktot) v = cent[r];
                pa[l] = v;
            }
#pragma unroll
            for (int l = 0; l < 8; l++) {
                int kk = b_kk0 + l * 2;
                int k = k0 + kk;
                pb[l] = (k < Ktot) ? W[(long)k * FF + col0 + b_n] : 0.f;
            }
        }
#pragma unroll
        for (int kk = 0; kk < BK; kk++) {
            float4 a0 = *(const float4*)&As[buf][kk][ty * 8];
            float4 a1 = *(const float4*)&As[buf][kk][ty * 8 + 4];
            float4 b0 = *(const float4*)&Bs[buf][kk][tx * 4];
            float ra[8] = {a0.x, a0.y, a0.z, a0.w, a1.x, a1.y, a1.z, a1.w};
            float rb[4] = {b0.x, b0.y, b0.z, b0.w};
#pragma unroll
            for (int i = 0; i < 8; i++)
#pragma unroll
                for (int j = 0; j < 4; j++) acc[i][j] = fmaf(ra[i], rb[j], acc[i][j]);
        }
        if (hasNext) {
            int nbuf = 1 - buf;
#pragma unroll
            for (int l = 0; l < 8; l++) As[nbuf][a_kk][a_m0 + l * 8] = pa[l];
#pragma unroll
            for (int l = 0; l < 8; l++) Bs[nbuf][b_kk0 + l * 2][b_n] = pb[l];
            __syncthreads();
        }
    }
#pragma unroll
    for (int i = 0; i < 8; i++) {
        int r = row0 + ty * 8 + i;
        long base = (long)r * FF + col0 + tx * 4;
#pragma unroll
        for (int j = 0; j < 4; j++) C[base + j] = acc[i][j];
        __half2* hdst = (__half2*)(CH + base);
        hdst[0] = __floats2half2_rn(acc[i][0], acc[i][1]);
        hdst[1] = __floats2half2_rn(acc[i][2], acc[i][3]);
    }
}

// ---------------- unpool: out[idx[i]][j] = X[i][j] * sigmoid((X @ W^T)[i][j] + b[j]) ----------------
#define BNP (BN + 4)
__global__ __launch_bounds__(128) void gemm_unpool(
    const float* __restrict__ X, const float* __restrict__ W,
    const float* __restrict__ b, const int* __restrict__ idxArr,
    float* __restrict__ out) {
    __shared__ float As[2][BK][BMP];
    __shared__ float Bs[2][BK][BNP];
    int tid = threadIdx.x;
    int row0 = blockIdx.y * BM;
    int col0 = blockIdx.x * BN;
    int tx = tid & 15, ty = tid >> 4;
    const int nT = FF / BK;   // 20
    float acc[8][4];
#pragma unroll
    for (int i = 0; i < 8; i++)
#pragma unroll
        for (int j = 0; j < 4; j++) acc[i][j] = 0.f;

    int a_kk = tid & 15, a_m0 = tid >> 4;
    int w_kk = tid & 15, w_n0 = tid >> 4;   // W^T loader: consecutive threads -> consecutive k

    {
#pragma unroll
        for (int l = 0; l < 8; l++)
            As[0][a_kk][a_m0 + l * 8] = X[(long)(row0 + a_m0 + l * 8) * FF + a_kk];
#pragma unroll
        for (int l = 0; l < 8; l++)
            Bs[0][w_kk][w_n0 + l * 8] = W[(long)(col0 + w_n0 + l * 8) * FF + w_kk];
    }
    __syncthreads();

    float pa[8], pb[8];
    for (int t = 0; t < nT; t++) {
        int buf = t & 1;
        bool hasNext = (t + 1 < nT);
        if (hasNext) {
            int k0 = (t + 1) * BK;
#pragma unroll
            for (int l = 0; l < 8; l++)
                pa[l] = X[(long)(row0 + a_m0 + l * 8) * FF + k0 + a_kk];
#pragma unroll
            for (int l = 0; l < 8; l++)
                pb[l] = W[(long)(col0 + w_n0 + l * 8) * FF + k0 + w_kk];
        }
#pragma unroll
        for (int kk = 0; kk < BK; kk++) {
            float4 a0 = *(const float4*)&As[buf][kk][ty * 8];
            float4 a1 = *(const float4*)&As[buf][kk][ty * 8 + 4];
            float4 b0 = *(const float4*)&Bs[buf][kk][tx * 4];
            float ra[8] = {a0.x, a0.y, a0.z, a0.w, a1.x, a1.y, a1.z, a1.w};
            float rb[4] = {b0.x, b0.y, b0.z, b0.w};
#pragma unroll
            for (int i = 0; i < 8; i++)
#pragma unroll
                for (int j = 0; j < 4; j++) acc[i][j] = fmaf(ra[i], rb[j], acc[i][j]);
        }
        if (hasNext) {
            int nbuf = 1 - buf;
#pragma unroll
            for (int l = 0; l < 8; l++) As[nbuf][a_kk][a_m0 + l * 8] = pa[l];
#pragma unroll
            for (int l = 0; l < 8; l++) Bs[nbuf][w_kk][w_n0 + l * 8] = pb[l];
            __syncthreads();
        }
    }
#pragma unroll
    for (int i = 0; i < 8; i++) {
        int r = row0 + ty * 8 + i;
        int dst = idxArr[r];
#pragma unroll
        for (int j = 0; j < 4; j++) {
            int c = col0 + tx * 4 + j;
            float aw = 1.f / (1.f + expf(-(acc[i][j] + b[c])));
            out[(long)dst * FF + c] = X[(long)r * FF + c] * aw;
        }
    }
}

// ---------------- s1/s2 = Wh @ a-halves (warp per row, fully unrolled for MLP) ----------------
__global__ void compute_s(const float* __restrict__ Wh, const float* __restrict__ a,
                          float* __restrict__ s1, float* __restrict__ s2) {
    int warp = (blockIdx.x * blockDim.x + threadIdx.x) >> 5;
    int lane = threadIdx.x & 31;
    if (warp >= NN) return;
    const float* row = Wh + (long)warp * FF;
    float w[10], a1v[10], a2v[10];
#pragma unroll
    for (int it = 0; it < 10; it++) {
        int t = lane + it * 32;
        w[it] = __ldg(row + t);
        a1v[it] = __ldg(a + t);
        a2v[it] = __ldg(a + FF + t);
    }
    float x1 = 0.f, x2 = 0.f;
#pragma unroll
    for (int it = 0; it < 10; it++) {
        x1 = fmaf(w[it], a1v[it], x1);
        x2 = fmaf(w[it], a2v[it], x2);
    }
    for (int o = 16; o; o >>= 1) {
        x1 += __shfl_down_sync(0xffffffffu, x1, o);
        x2 += __shfl_down_sync(0xffffffffu, x2, o);
    }
    if (lane == 0) { s1[warp] = x1; s2[warp] = x2; }
}

// ---------------- pool scores: sigmoid((X@w + b)/100) (warp per row) ----------------
__global__ void scores_k(const float* __restrict__ X, const float* __restrict__ w,
                         const float* __restrict__ b, float* __restrict__ sc) {
    int warp = (blockIdx.x * blockDim.x + threadIdx.x) >> 5;
    int lane = threadIdx.x & 31;
    if (warp >= NN) return;
    const float* row = X + (long)warp * FF;
    float z = 0.f;
#pragma unroll
    for (int it = 0; it < 10; it++) {
        int t = lane + it * 32;
        z = fmaf(__ldg(row + t), __ldg(w + t), z);
    }
    for (int o = 16; o; o >>= 1) z += __shfl_down_sync(0xffffffffu, z, o);
    if (lane == 0) {
        float v = (z + b[0]) * 0.01f;
        sc[warp] = 1.f / (1.f + expf(-v));
    }
}

// ---------------- stable descending rank (top_k with k=N semantics) ----------------
__global__ void rank_kernel(const float* __restrict__ s, int* __restrict__ idxArr) {
    __shared__ int red[256];
    int i = blockIdx.x;
    int tid = threadIdx.x;
    float si = s[i];
    int cnt = 0;
    for (int j = tid; j < NN; j += 256) {
        float sj = s[j];
        cnt += (sj > si) || (sj == si && j < i);
    }
    red[tid] = cnt;
    __syncthreads();
    for (int st = 128; st > 0; st >>= 1) {
        if (tid < st) red[tid] += red[tid + st];
        __syncthreads();
    }
    if (tid == 0) idxArr[red[0]] = i;
}

// ---------------- apply pool: permute X*value, update perm + inverse ----------------
__global__ void pool_apply(const float* __restrict__ Xold, const float* __restrict__ sc,
                           const int* __restrict__ idxArr, const int* __restrict__ pOld,
                           int* __restrict__ pNew, int* __restrict__ pinvNew,
                           float* __restrict__ Xnew) {
    int r = blockIdx.x;
    int o = idxArr[r];
    if (threadIdx.x == 0) {
        int po = pOld[o];
        pNew[r] = po;
        pinvNew[po] = r;
    }
    float v = sc[o];
    int t = threadIdx.x;
    Xnew[(long)r * FF + t] = Xold[(long)o * FF + t] * v;
}

// ---------------- sparse GAT attention + aggregation (block per row, 160 threads, half2 gathers) ----------------
__global__ __launch_bounds__(160) void attn_kernel(
    const __half2* __restrict__ WhH, const float* __restrict__ s1,
    const float* __restrict__ s2, const int* __restrict__ cols,
    const int* __restrict__ deg, const int* __restrict__ p,
    const int* __restrict__ pinv, const float* __restrict__ resid,
    float* __restrict__ out, int applyElu, float* __restrict__ out2) {
    __shared__ int nb[MAXDEG];      // stores r*FH (half2 row offset)
    __shared__ float ev[MAXDEG];
    __shared__ float redw[8];
    int i = blockIdx.x;
    int tid = threadIdx.x;
    int wid = tid >> 5, lane = tid & 31;
    int orig = p[i];
    int d = deg[orig];
    float si = s1[i];
    for (int k = tid; k < d; k += 160) {
        int c = __ldg(cols + (long)orig * MAXDEG + k);
        int r = __ldg(pinv + c);
        nb[k] = r * FH;
        float e = si + __ldg(s2 + r);
        ev[k] = e > 0.f ? e : 0.2f * e;   // leaky_relu(0.2)
    }
    __syncthreads();
    // max reduce (5 warps)
    float m = -FLT_MAX;
    for (int k = tid; k < d; k += 160) m = fmaxf(m, ev[k]);
    for (int o = 16; o; o >>= 1) m = fmaxf(m, __shfl_xor_sync(0xffffffffu, m, o));
    if (lane == 0) redw[wid] = m;
    __syncthreads();
    if (tid < 32) {
        float v = (tid < 5) ? redw[tid] : -FLT_MAX;
        for (int o = 16; o; o >>= 1) v = fmaxf(v, __shfl_xor_sync(0xffffffffu, v, o));
        if (tid == 0) redw[0] = v;
    }
    __syncthreads();
    m = redw[0];
    // exp & sum
    float ssum = 0.f;
    for (int k = tid; k < d; k += 160) {
        float e = __expf(ev[k] - m);
        ev[k] = e;
        ssum += e;
    }
    for (int o = 16; o; o >>= 1) ssum += __shfl_xor_sync(0xffffffffu, ssum, o);
    __syncthreads();
    if (lane == 0) redw[wid] = ssum;
    __syncthreads();
    if (tid < 32) {
        float v = (tid < 5) ? redw[tid] : 0.f;
        for (int o = 16; o; o >>= 1) v += __shfl_xor_sync(0xffffffffu, v, o);
        if (tid == 0) redw[0] = v;
    }
    __syncthreads();
    float inv = 1.f / redw[0];
    // aggregate: one half2 column-pair per thread, fp32 accumulate, unroll x8
    int j = tid;   // 0..159
    float ax[8], ay[8];
#pragma unroll
    for (int u = 0; u < 8; u++) { ax[u] = 0.f; ay[u] = 0.f; }
    int d8 = d & ~7;
    int k = 0;
    for (; k < d8; k += 8) {
        float2 f[8];
        float e[8];
#pragma unroll
        for (int u = 0; u < 8; u++) {
            f[u] = __half22float2(__ldg(WhH + nb[k + u] + j));
            e[u] = ev[k + u];
        }
#pragma unroll
        for (int u = 0; u < 8; u++) {
            ax[u] = fmaf(e[u], f[u].x, ax[u]);
            ay[u] = fmaf(e[u], f[u].y, ay[u]);
        }
    }
    for (; k < d; k++) {
        float2 f = __half22float2(__ldg(WhH + nb[k] + j));
        float e = ev[k];
        ax[0] = fmaf(e, f.x, ax[0]);
        ay[0] = fmaf(e, f.y, ay[0]);
    }
    float accx = (((ax[0] + ax[1]) + (ax[2] + ax[3])) + ((ax[4] + ax[5]) + (ax[6] + ax[7]))) * inv;
    float accy = (((ay[0] + ay[1]) + (ay[2] + ay[3])) + ((ay[4] + ay[5]) + (ay[6] + ay[7]))) * inv;
    if (applyElu) {
        accx = accx > 0.f ? accx : expm1f(accx);
        accy = accy > 0.f ? accy : expm1f(accy);
    }
    long base = (long)i * FF + 2 * j;
    if (resid) {
        accx += resid[base];
        accy += resid[base + 1];
    }
    out[base] = accx;
    out[base + 1] = accy;
    if (out2) {
        out2[base] = accx;
        out2[base + 1] = accy;
    }
}

// ---------------- host driver ----------------
static void* sym(const void* s) {
    void* p = nullptr;
    cudaGetSymbolAddress(&p, s);
    return p;
}

extern "C" void kernel_launch(void* const* d_in, const int* in_sizes, int n_in,
                              void* d_out, int out_size) {
    const float* A        = (const float*)d_in[0];
    const float* X        = (const float*)d_in[1];
    const float* start_W  = (const float*)d_in[2];
    const float* start_a  = (const float*)d_in[3];
    const float* bottom_W = (const float*)d_in[4];
    const float* bottom_a = (const float*)d_in[5];
    const float* end_W    = (const float*)d_in[6];
    const float* end_a    = (const float*)d_in[7];
    const float* down_W0  = (const float*)d_in[8];
    const float* down_a0  = (const float*)d_in[9];
    const float* up_W0    = (const float*)d_in[10];
    const float* up_a0    = (const float*)d_in[11];
    const float* pool_w0  = (const float*)d_in[12];
    const float* pool_b0  = (const float*)d_in[13];
    const float* unpool_w0= (const float*)d_in[14];
    const float* unpool_b0= (const float*)d_in[15];
    const float* down_W1  = (const float*)d_in[16];
    const float* down_a1  = (const float*)d_in[17];
    const float* up_W1    = (const float*)d_in[18];
    const float* up_a1    = (const float*)d_in[19];
    const float* pool_w1  = (const float*)d_in[20];
    const float* pool_b1  = (const float*)d_in[21];
    const float* unpool_w1= (const float*)d_in[22];
    const float* unpool_b1= (const float*)d_in[23];

    float* Wh    = (float*)sym(g_Wh);
    __half* WhH  = (__half*)sym(g_WhH);
    float* org   = (float*)sym(g_org);
    float* D0    = (float*)sym(g_D0);
    float* D1    = (float*)sym(g_D1);
    float* bA    = (float*)sym(g_bA);
    float* bB    = (float*)sym(g_bB);
    float* cent  = (float*)sym(g_cent);
    float* s1    = (float*)sym(g_s1);
    float* s2    = (float*)sym(g_s2);
    float* sc    = (float*)sym(g_sc);
    int* cols = (int*)sym(g_cols);
    int* deg  = (int*)sym(g_deg);
    int* idp  = (int*)sym(g_idp);
    int* p1   = (int*)sym(g_p1);
    int* p2   = (int*)sym(g_p2);
    int* pi1  = (int*)sym(g_pi1);
    int* pi2  = (int*)sym(g_pi2);
    int* i0   = (int*)sym(g_i0);
    int* i1   = (int*)sym(g_i1);

    float* outX = (float*)d_out;
    float* out2 = outX + (long)NN * FF;   // second output = start_out
    const __half2* WhH2 = (const __half2*)WhH;

    dim3 gemmGrid(FF / BN, NN / BM);   // (5, 64) = 320 blocks

    // adjacency + centrality + identity perm
    build_adj<<<NN / 8, 256>>>(A, cols, deg, cent, idp);

    // start GAT: [X | cent | cent] @ start_W -> org (elu); also writes d_out second half
    gemm_cat<<<gemmGrid, 128>>>(X, FF, nullptr, 0, 2, cent, start_W, Wh, WhH);
    compute_s<<<NN / 8, 256>>>(Wh, start_a, s1, s2);
    attn_kernel<<<NN, 160>>>(WhH2, s1, s2, cols, deg, idp, idp, nullptr, org, 1, out2);

    // down0 GAT (level 0) -> D0
    gemm_cat<<<gemmGrid, 128>>>(org, FF, nullptr, 0, 1, cent, down_W0, Wh, WhH);
    compute_s<<<NN / 8, 256>>>(Wh, down_a0, s1, s2);
    attn_kernel<<<NN, 160>>>(WhH2, s1, s2, cols, deg, idp, idp, nullptr, D0, 1, nullptr);

    // pool 0
    scores_k<<<NN / 8, 256>>>(D0, pool_w0, pool_b0, sc);
    rank_kernel<<<NN, 256>>>(sc, i0);
    pool_apply<<<NN, 320>>>(D0, sc, i0, idp, p1, pi1, bA);

    // down1 GAT (level 1, perm p1) -> D1
    gemm_cat<<<gemmGrid, 128>>>(bA, FF, nullptr, 0, 1, cent, down_W1, Wh, WhH);
    compute_s<<<NN / 8, 256>>>(Wh, down_a1, s1, s2);
    attn_kernel<<<NN, 160>>>(WhH2, s1, s2, cols, deg, p1, pi1, nullptr, D1, 1, nullptr);

    // pool 1
    scores_k<<<NN / 8, 256>>>(D1, pool_w1, pool_b1, sc);
    rank_kernel<<<NN, 256>>>(sc, i1);
    pool_apply<<<NN, 320>>>(D1, sc, i1, p1, p2, pi2, bA);

    // bottom GAT (level 2, perm p2) -> bB
    gemm_cat<<<gemmGrid, 128>>>(bA, FF, nullptr, 0, 1, cent, bottom_W, Wh, WhH);
    compute_s<<<NN / 8, 256>>>(Wh, bottom_a, s1, s2);
    attn_kernel<<<NN, 160>>>(WhH2, s1, s2, cols, deg, p2, pi2, nullptr, bB, 1, nullptr);

    // unpool 0 (scatter via i1 -> level 1)
    gemm_unpool<<<gemmGrid, 128>>>(bB, unpool_w0, unpool_b0, i1, bA);

    // up0 GAT (level 1, perm p1) -> bB (+D1 residual fused)
    gemm_cat<<<gemmGrid, 128>>>(bA, FF, nullptr, 0, 1, cent, up_W0, Wh, WhH);
    compute_s<<<NN / 8, 256>>>(Wh, up_a0, s1, s2);
    attn_kernel<<<NN, 160>>>(WhH2, s1, s2, cols, deg, p1, pi1, D1, bB, 1, nullptr);

    // unpool 1 (scatter via i0 -> level 0)
    gemm_unpool<<<gemmGrid, 128>>>(bB, unpool_w1, unpool_b1, i0, bA);

    // up1 GAT (level 0, identity perm) -> bB (+D0 residual fused)
    gemm_cat<<<gemmGrid, 128>>>(bA, FF, nullptr, 0, 1, cent, up_W1, Wh, WhH);
    compute_s<<<NN / 8, 256>>>(Wh, up_a1, s1, s2);
    attn_kernel<<<NN, 160>>>(WhH2, s1, s2, cols, deg, idp, idp, D0, bB, 1, nullptr);

    // end GAT: [bB | org | cent] @ end_W (concat fused into loader), no elu -> d_out
    gemm_cat<<<gemmGrid, 128>>>(bB, FF, org, FF, 1, cent, end_W, Wh, WhH);
    compute_s<<<NN / 8, 256>>>(Wh, end_a, s1, s2);
    attn_kernel<<<NN, 160>>>(WhH2, s1, s2, cols, deg, idp, idp, nullptr, outX, 0, nullptr);
}

// round 6
// speedup vs baseline: 2.1048x; 1.0900x over previous
#include <cuda_runtime.h>
#include <cuda_fp16.h>
#include <math.h>
#include <float.h>

#define NN 4096
#define FF 320
#define FH 160          // FF/2 (half2 columns)
#define MAXDEG 768
#define RPB 4           // rows per attn block
#define TPR 80          // threads per row (80 * uint2 = 320 floats)

// ---------------- scratch (static __device__ globals; no allocations) ----------------
__device__ float g_Wh[NN * FF];
__device__ __half g_WhH[NN * FF];
__device__ float g_org[NN * FF];
__device__ float g_D0[NN * FF];
__device__ float g_D1[NN * FF];
__device__ float g_bA[NN * FF];
__device__ float g_bB[NN * FF];
__device__ float g_cent[NN];
__device__ float g_s1[NN];
__device__ float g_s2[NN];
__device__ float g_sc[NN];
__device__ int g_cols[NN * MAXDEG];
__device__ int g_deg[NN];
__device__ int g_idp[NN];
__device__ int g_p1[NN];
__device__ int g_p2[NN];
__device__ int g_pi1[NN];
__device__ int g_pi2[NN];
__device__ int g_i0[NN];
__device__ int g_i1[NN];

// ---------------- adjacency ELL build + degree centrality + identity perm (warp per row) ----------------
__global__ void build_adj(const float* __restrict__ A, int* __restrict__ cols,
                          int* __restrict__ deg, float* __restrict__ cent,
                          int* __restrict__ idp) {
    int warp = (blockIdx.x * blockDim.x + threadIdx.x) >> 5;
    int lane = threadIdx.x & 31;
    if (warp >= NN) return;
    long rowoff = (long)warp * NN;
    float sum = 0.f;
    int base = 0;
    for (int c0 = 0; c0 < NN; c0 += 32) {
        float v = A[rowoff + c0 + lane];
        sum += v;
        unsigned m = __ballot_sync(0xffffffffu, v > 0.f);
        if (v > 0.f) {
            int pos = base + __popc(m & ((1u << lane) - 1u));
            if (pos < MAXDEG) cols[(long)warp * MAXDEG + pos] = c0 + lane;
        }
        base += __popc(m);
    }
    for (int o = 16; o; o >>= 1) sum += __shfl_xor_sync(0xffffffffu, sum, o);
    if (lane == 0) {
        deg[warp] = base < MAXDEG ? base : MAXDEG;
        cent[warp] = sum / (float)(NN - 1);
        idp[warp] = warp;
    }
}

// ---------------- GEMM: C = [X1 | X2 | cent*nc] @ W ; also emits half copy CH ----------------
#define BM 64
#define BN 64
#define BK 16
#define BMP (BM + 4)

__global__ __launch_bounds__(128) void gemm_cat(
    const float* __restrict__ X1, int K1,
    const float* __restrict__ X2, int K2,
    int nc, const float* __restrict__ cent,
    const float* __restrict__ W, float* __restrict__ C,
    __half* __restrict__ CH) {
    __shared__ float As[2][BK][BMP];
    __shared__ float Bs[2][BK][BN];
    int tid = threadIdx.x;
    int row0 = blockIdx.y * BM;
    int col0 = blockIdx.x * BN;
    int K12 = K1 + K2;
    int Ktot = K12 + nc;
    int nT = (Ktot + BK - 1) / BK;
    int tx = tid & 15, ty = tid >> 4;
    float acc[8][4];
#pragma unroll
    for (int i = 0; i < 8; i++)
#pragma unroll
        for (int j = 0; j < 4; j++) acc[i][j] = 0.f;

    int a_kk = tid & 15, a_m0 = tid >> 4;
    int b_n = tid & 63, b_kk0 = tid >> 6;

    {
        int k0 = 0;
#pragma unroll
        for (int l = 0; l < 8; l++) {
            int m = a_m0 + l * 8;
            int k = k0 + a_kk;
            int r = row0 + m;
            float v = 0.f;
            if (k < K1) v = X1[(long)r * K1 + k];
            else if (k < K12) v = X2[(long)r * K2 + (k - K1)];
            else if (k < Ktot) v = cent[r];
            As[0][a_kk][m] = v;
        }
#pragma unroll
        for (int l = 0; l < 8; l++) {
            int kk = b_kk0 + l * 2;
            int k = k0 + kk;
            Bs[0][kk][b_n] = (k < Ktot) ? W[(long)k * FF + col0 + b_n] : 0.f;
        }
    }
    __syncthreads();

    float pa[8], pb[8];
    for (int t = 0; t < nT; t++) {
        int buf = t & 1;
        bool hasNext = (t + 1 < nT);
        if (hasNext) {
            int k0 = (t + 1) * BK;
#pragma unroll
            for (int l = 0; l < 8; l++) {
                int m = a_m0 + l * 8;
                int k = k0 + a_kk;
                int r = row0 + m;
                float v = 0.f;
                if (k < K1) v = X1[(long)r * K1 + k];
                else if (k < K12) v = X2[(long)r * K2 + (k - K1)];
                else if (k < Ktot) v = cent[r];
                pa[l] = v;
            }
#pragma unroll
            for (int l = 0; l < 8; l++) {
                int kk = b_kk0 + l * 2;
                int k = k0 + kk;
                pb[l] = (k < Ktot) ? W[(long)k * FF + col0 + b_n] : 0.f;
            }
        }
#pragma unroll
        for (int kk = 0; kk < BK; kk++) {
            float4 a0 = *(const float4*)&As[buf][kk][ty * 8];
            float4 a1 = *(const float4*)&As[buf][kk][ty * 8 + 4];
            float4 b0 = *(const float4*)&Bs[buf][kk][tx * 4];
            float ra[8] = {a0.x, a0.y, a0.z, a0.w, a1.x, a1.y, a1.z, a1.w};
            float rb[4] = {b0.x, b0.y, b0.z, b0.w};
#pragma unroll
            for (int i = 0; i < 8; i++)
#pragma unroll
                for (int j = 0; j < 4; j++) acc[i][j] = fmaf(ra[i], rb[j], acc[i][j]);
        }
        if (hasNext) {
            int nbuf = 1 - buf;
#pragma unroll
            for (int l = 0; l < 8; l++) As[nbuf][a_kk][a_m0 + l * 8] = pa[l];
#pragma unroll
            for (int l = 0; l < 8; l++) Bs[nbuf][b_kk0 + l * 2][b_n] = pb[l];
            __syncthreads();
        }
    }
#pragma unroll
    for (int i = 0; i < 8; i++) {
        int r = row0 + ty * 8 + i;
        long base = (long)r * FF + col0 + tx * 4;
#pragma unroll
        for (int j = 0; j < 4; j++) C[base + j] = acc[i][j];
        __half2* hdst = (__half2*)(CH + base);
        hdst[0] = __floats2half2_rn(acc[i][0], acc[i][1]);
        hdst[1] = __floats2half2_rn(acc[i][2], acc[i][3]);
    }
}

// ---------------- unpool: out[idx[i]][j] = X[i][j] * sigmoid((X @ W^T)[i][j] + b[j]) ----------------
#define BNP (BN + 4)
__global__ __launch_bounds__(128) void gemm_unpool(
    const float* __restrict__ X, const float* __restrict__ W,
    const float* __restrict__ b, const int* __restrict__ idxArr,
    float* __restrict__ out) {
    __shared__ float As[2][BK][BMP];
    __shared__ float Bs[2][BK][BNP];
    int tid = threadIdx.x;
    int row0 = blockIdx.y * BM;
    int col0 = blockIdx.x * BN;
    int tx = tid & 15, ty = tid >> 4;
    const int nT = FF / BK;   // 20
    float acc[8][4];
#pragma unroll
    for (int i = 0; i < 8; i++)
#pragma unroll
        for (int j = 0; j < 4; j++) acc[i][j] = 0.f;

    int a_kk = tid & 15, a_m0 = tid >> 4;
    int w_kk = tid & 15, w_n0 = tid >> 4;

    {
#pragma unroll
        for (int l = 0; l < 8; l++)
            As[0][a_kk][a_m0 + l * 8] = X[(long)(row0 + a_m0 + l * 8) * FF + a_kk];
#pragma unroll
        for (int l = 0; l < 8; l++)
            Bs[0][w_kk][w_n0 + l * 8] = W[(long)(col0 + w_n0 + l * 8) * FF + w_kk];
    }
    __syncthreads();

    float pa[8], pb[8];
    for (int t = 0; t < nT; t++) {
        int buf = t & 1;
        bool hasNext = (t + 1 < nT);
        if (hasNext) {
            int k0 = (t + 1) * BK;
#pragma unroll
            for (int l = 0; l < 8; l++)
                pa[l] = X[(long)(row0 + a_m0 + l * 8) * FF + k0 + a_kk];
#pragma unroll
            for (int l = 0; l < 8; l++)
                pb[l] = W[(long)(col0 + w_n0 + l * 8) * FF + k0 + w_kk];
        }
#pragma unroll
        for (int kk = 0; kk < BK; kk++) {
            float4 a0 = *(const float4*)&As[buf][kk][ty * 8];
            float4 a1 = *(const float4*)&As[buf][kk][ty * 8 + 4];
            float4 b0 = *(const float4*)&Bs[buf][kk][tx * 4];
            float ra[8] = {a0.x, a0.y, a0.z, a0.w, a1.x, a1.y, a1.z, a1.w};
            float rb[4] = {b0.x, b0.y, b0.z, b0.w};
#pragma unroll
            for (int i = 0; i < 8; i++)
#pragma unroll
                for (int j = 0; j < 4; j++) acc[i][j] = fmaf(ra[i], rb[j], acc[i][j]);
        }
        if (hasNext) {
            int nbuf = 1 - buf;
#pragma unroll
            for (int l = 0; l < 8; l++) As[nbuf][a_kk][a_m0 + l * 8] = pa[l];
#pragma unroll
            for (int l = 0; l < 8; l++) Bs[nbuf][w_kk][w_n0 + l * 8] = pb[l];
            __syncthreads();
        }
    }
#pragma unroll
    for (int i = 0; i < 8; i++) {
        int r = row0 + ty * 8 + i;
        int dst = idxArr[r];
#pragma unroll
        for (int j = 0; j < 4; j++) {
            int c = col0 + tx * 4 + j;
            float aw = 1.f / (1.f + expf(-(acc[i][j] + b[c])));
            out[(long)dst * FF + c] = X[(long)r * FF + c] * aw;
        }
    }
}

// ---------------- s1/s2 = Wh @ a-halves (warp per row, fully unrolled) ----------------
__global__ void compute_s(const float* __restrict__ Wh, const float* __restrict__ a,
                          float* __restrict__ s1, float* __restrict__ s2) {
    int warp = (blockIdx.x * blockDim.x + threadIdx.x) >> 5;
    int lane = threadIdx.x & 31;
    if (warp >= NN) return;
    const float* row = Wh + (long)warp * FF;
    float w[10], a1v[10], a2v[10];
#pragma unroll
    for (int it = 0; it < 10; it++) {
        int t = lane + it * 32;
        w[it] = __ldg(row + t);
        a1v[it] = __ldg(a + t);
        a2v[it] = __ldg(a + FF + t);
    }
    float x1 = 0.f, x2 = 0.f;
#pragma unroll
    for (int it = 0; it < 10; it++) {
        x1 = fmaf(w[it], a1v[it], x1);
        x2 = fmaf(w[it], a2v[it], x2);
    }
    for (int o = 16; o; o >>= 1) {
        x1 += __shfl_down_sync(0xffffffffu, x1, o);
        x2 += __shfl_down_sync(0xffffffffu, x2, o);
    }
    if (lane == 0) { s1[warp] = x1; s2[warp] = x2; }
}

// ---------------- pool scores: sigmoid((X@w + b)/100) (warp per row) ----------------
__global__ void scores_k(const float* __restrict__ X, const float* __restrict__ w,
                         const float* __restrict__ b, float* __restrict__ sc) {
    int warp = (blockIdx.x * blockDim.x + threadIdx.x) >> 5;
    int lane = threadIdx.x & 31;
    if (warp >= NN) return;
    const float* row = X + (long)warp * FF;
    float z = 0.f;
#pragma unroll
    for (int it = 0; it < 10; it++) {
        int t = lane + it * 32;
        z = fmaf(__ldg(row + t), __ldg(w + t), z);
    }
    for (int o = 16; o; o >>= 1) z += __shfl_down_sync(0xffffffffu, z, o);
    if (lane == 0) {
        float v = (z + b[0]) * 0.01f;
        sc[warp] = 1.f / (1.f + expf(-v));
    }
}

// ---------------- stable descending rank (top_k with k=N semantics) ----------------
__global__ void rank_kernel(const float* __restrict__ s, int* __restrict__ idxArr) {
    __shared__ int red[256];
    int i = blockIdx.x;
    int tid = threadIdx.x;
    float si = s[i];
    int cnt = 0;
    for (int j = tid; j < NN; j += 256) {
        float sj = s[j];
        cnt += (sj > si) || (sj == si && j < i);
    }
    red[tid] = cnt;
    __syncthreads();
    for (int st = 128; st > 0; st >>= 1) {
        if (tid < st) red[tid] += red[tid + st];
        __syncthreads();
    }
    if (tid == 0) idxArr[red[0]] = i;
}

// ---------------- apply pool: permute X*value, update perm + inverse ----------------
__global__ void pool_apply(const float* __restrict__ Xold, const float* __restrict__ sc,
                           const int* __restrict__ idxArr, const int* __restrict__ pOld,
                           int* __restrict__ pNew, int* __restrict__ pinvNew,
                           float* __restrict__ Xnew) {
    int r = blockIdx.x;
    int o = idxArr[r];
    if (threadIdx.x == 0) {
        int po = pOld[o];
        pNew[r] = po;
        pinvNew[po] = r;
    }
    float v = sc[o];
    int t = threadIdx.x;
    Xnew[(long)r * FF + t] = Xold[(long)o * FF + t] * v;
}

// ---------------- sparse GAT attention: 4 rows/block, 80 threads/row, uint2 gathers ----------------
__global__ __launch_bounds__(RPB * TPR) void attn_kernel(
    const __half2* __restrict__ WhH, const float* __restrict__ s1,
    const float* __restrict__ s2, const int* __restrict__ cols,
    const int* __restrict__ deg, const int* __restrict__ p,
    const int* __restrict__ pinv, const float* __restrict__ resid,
    float* __restrict__ out, int applyElu, float* __restrict__ out2) {
    __shared__ float2 pk[RPB][MAXDEG];   // .x = byte offset (int bits), .y = score
    __shared__ float red[RPB][TPR];
    int tid = threadIdx.x;
    int r = tid / TPR, t = tid - r * TPR;
    int i = blockIdx.x * RPB + r;
    int orig = p[i];
    int d = deg[orig];
    float si = s1[i];
    // fill neighbor workspace; WhH row stride = FH half2 = FH*4 bytes
    for (int k = t; k < d; k += TPR) {
        int c = __ldg(cols + (long)orig * MAXDEG + k);
        int rr = __ldg(pinv + c);
        float e = si + __ldg(s2 + rr);
        e = e > 0.f ? e : 0.2f * e;   // leaky_relu(0.2)
        pk[r][k] = make_float2(__int_as_float(rr * (FH * 4)), e);
    }
    __syncthreads();
    // max reduce
    float m = -FLT_MAX;
    for (int k = t; k < d; k += TPR) m = fmaxf(m, pk[r][k].y);
    red[r][t] = m;
    __syncthreads();
#pragma unroll
    for (int s = 64; s > 0; s >>= 1) {
        if (t < s && t + s < TPR) red[r][t] = fmaxf(red[r][t], red[r][t + s]);
        __syncthreads();
    }
    m = red[r][0];
    __syncthreads();
    // exp & sum
    float ssum = 0.f;
    for (int k = t; k < d; k += TPR) {
        float e = __expf(pk[r][k].y - m);
        pk[r][k].y = e;
        ssum += e;
    }
    red[r][t] = ssum;
    __syncthreads();
#pragma unroll
    for (int s = 64; s > 0; s >>= 1) {
        if (t < s && t + s < TPR) red[r][t] += red[r][t + s];
        __syncthreads();
    }
    float inv = 1.f / red[r][0];
    // aggregation: thread t covers half2 columns 2t, 2t+1 (floats 4t..4t+3)
    const char* basep = (const char*)WhH + t * 8;
    float acc[2][4];
#pragma unroll
    for (int u = 0; u < 2; u++)
#pragma unroll
        for (int c = 0; c < 4; c++) acc[u][c] = 0.f;
    int d8 = d & ~7;
    int k = 0;
    for (; k < d8; k += 8) {
        float2 pe[8];
        uint2 v[8];
#pragma unroll
        for (int u = 0; u < 8; u++) pe[u] = pk[r][k + u];
#pragma unroll
        for (int u = 0; u < 8; u++)
            v[u] = __ldg((const uint2*)(basep + __float_as_int(pe[u].x)));
#pragma unroll
        for (int u = 0; u < 8; u++) {
            float2 f0 = __half22float2(*(const __half2*)&v[u].x);
            float2 f1 = __half22float2(*(const __half2*)&v[u].y);
            int s = u & 1;
            float e = pe[u].y;
            acc[s][0] = fmaf(e, f0.x, acc[s][0]);
            acc[s][1] = fmaf(e, f0.y, acc[s][1]);
            acc[s][2] = fmaf(e, f1.x, acc[s][2]);
            acc[s][3] = fmaf(e, f1.y, acc[s][3]);
        }
    }
    for (; k < d; k++) {
        float2 pe = pk[r][k];
        uint2 v = __ldg((const uint2*)(basep + __float_as_int(pe.x)));
        float2 f0 = __half22float2(*(const __half2*)&v.x);
        float2 f1 = __half22float2(*(const __half2*)&v.y);
        float e = pe.y;
        acc[0][0] = fmaf(e, f0.x, acc[0][0]);
        acc[0][1] = fmaf(e, f0.y, acc[0][1]);
        acc[0][2] = fmaf(e, f1.x, acc[0][2]);
        acc[0][3] = fmaf(e, f1.y, acc[0][3]);
    }
    float4 o4;
    o4.x = (acc[0][0] + acc[1][0]) * inv;
    o4.y = (acc[0][1] + acc[1][1]) * inv;
    o4.z = (acc[0][2] + acc[1][2]) * inv;
    o4.w = (acc[0][3] + acc[1][3]) * inv;
    if (applyElu) {
        o4.x = o4.x > 0.f ? o4.x : expm1f(o4.x);
        o4.y = o4.y > 0.f ? o4.y : expm1f(o4.y);
        o4.z = o4.z > 0.f ? o4.z : expm1f(o4.z);
        o4.w = o4.w > 0.f ? o4.w : expm1f(o4.w);
    }
    long base = (long)i * FF + 4 * t;
    if (resid) {
        float4 rv = *(const float4*)(resid + base);
        o4.x += rv.x; o4.y += rv.y; o4.z += rv.z; o4.w += rv.w;
    }
    *(float4*)(out + base) = o4;
    if (out2) *(float4*)(out2 + base) = o4;
}

// ---------------- host driver ----------------
static void* sym(const void* s) {
    void* p = nullptr;
    cudaGetSymbolAddress(&p, s);
    return p;
}

extern "C" void kernel_launch(void* const* d_in, const int* in_sizes, int n_in,
                              void* d_out, int out_size) {
    const float* A        = (const float*)d_in[0];
    const float* X        = (const float*)d_in[1];
    const float* start_W  = (const float*)d_in[2];
    const float* start_a  = (const float*)d_in[3];
    const float* bottom_W = (const float*)d_in[4];
    const float* bottom_a = (const float*)d_in[5];
    const float* end_W    = (const float*)d_in[6];
    const float* end_a    = (const float*)d_in[7];
    const float* down_W0  = (const float*)d_in[8];
    const float* down_a0  = (const float*)d_in[9];
    const float* up_W0    = (const float*)d_in[10];
    const float* up_a0    = (const float*)d_in[11];
    const float* pool_w0  = (const float*)d_in[12];
    const float* pool_b0  = (const float*)d_in[13];
    const float* unpool_w0= (const float*)d_in[14];
    const float* unpool_b0= (const float*)d_in[15];
    const float* down_W1  = (const float*)d_in[16];
    const float* down_a1  = (const float*)d_in[17];
    const float* up_W1    = (const float*)d_in[18];
    const float* up_a1    = (const float*)d_in[19];
    const float* pool_w1  = (const float*)d_in[20];
    const float* pool_b1  = (const float*)d_in[21];
    const float* unpool_w1= (const float*)d_in[22];
    const float* unpool_b1= (const float*)d_in[23];

    float* Wh    = (float*)sym(g_Wh);
    __half* WhH  = (__half*)sym(g_WhH);
    float* org   = (float*)sym(g_org);
    float* D0    = (float*)sym(g_D0);
    float* D1    = (float*)sym(g_D1);
    float* bA    = (float*)sym(g_bA);
    float* bB    = (float*)sym(g_bB);
    float* cent  = (float*)sym(g_cent);
    float* s1    = (float*)sym(g_s1);
    float* s2    = (float*)sym(g_s2);
    float* sc    = (float*)sym(g_sc);
    int* cols = (int*)sym(g_cols);
    int* deg  = (int*)sym(g_deg);
    int* idp  = (int*)sym(g_idp);
    int* p1   = (int*)sym(g_p1);
    int* p2   = (int*)sym(g_p2);
    int* pi1  = (int*)sym(g_pi1);
    int* pi2  = (int*)sym(g_pi2);
    int* i0   = (int*)sym(g_i0);
    int* i1   = (int*)sym(g_i1);

    float* outX = (float*)d_out;
    float* out2 = outX + (long)NN * FF;   // second output = start_out
    const __half2* WhH2 = (const __half2*)WhH;

    dim3 gemmGrid(FF / BN, NN / BM);   // (5, 64) = 320 blocks
    int attnGrid = NN / RPB;           // 1024
    int attnBlk = RPB * TPR;           // 320

    build_adj<<<NN / 8, 256>>>(A, cols, deg, cent, idp);

    // start GAT
    gemm_cat<<<gemmGrid, 128>>>(X, FF, nullptr, 0, 2, cent, start_W, Wh, WhH);
    compute_s<<<NN / 8, 256>>>(Wh, start_a, s1, s2);
    attn_kernel<<<attnGrid, attnBlk>>>(WhH2, s1, s2, cols, deg, idp, idp, nullptr, org, 1, out2);

    // down0 GAT
    gemm_cat<<<gemmGrid, 128>>>(org, FF, nullptr, 0, 1, cent, down_W0, Wh, WhH);
    compute_s<<<NN / 8, 256>>>(Wh, down_a0, s1, s2);
    attn_kernel<<<attnGrid, attnBlk>>>(WhH2, s1, s2, cols, deg, idp, idp, nullptr, D0, 1, nullptr);

    // pool 0
    scores_k<<<NN / 8, 256>>>(D0, pool_w0, pool_b0, sc);
    rank_kernel<<<NN, 256>>>(sc, i0);
    pool_apply<<<NN, 320>>>(D0, sc, i0, idp, p1, pi1, bA);

    // down1 GAT
    gemm_cat<<<gemmGrid, 128>>>(bA, FF, nullptr, 0, 1, cent, down_W1, Wh, WhH);
    compute_s<<<NN / 8, 256>>>(Wh, down_a1, s1, s2);
    attn_kernel<<<attnGrid, attnBlk>>>(WhH2, s1, s2, cols, deg, p1, pi1, nullptr, D1, 1, nullptr);

    // pool 1
    scores_k<<<NN / 8, 256>>>(D1, pool_w1, pool_b1, sc);
    rank_kernel<<<NN, 256>>>(sc, i1);
    pool_apply<<<NN, 320>>>(D1, sc, i1, p1, p2, pi2, bA);

    // bottom GAT
    gemm_cat<<<gemmGrid, 128>>>(bA, FF, nullptr, 0, 1, cent, bottom_W, Wh, WhH);
    compute_s<<<NN / 8, 256>>>(Wh, bottom_a, s1, s2);
    attn_kernel<<<attnGrid, attnBlk>>>(WhH2, s1, s2, cols, deg, p2, pi2, nullptr, bB, 1, nullptr);

    // unpool 0
    gemm_unpool<<<gemmGrid, 128>>>(bB, unpool_w0, unpool_b0, i1, bA);

    // up0 GAT (+D1 residual fused)
    gemm_cat<<<gemmGrid, 128>>>(bA, FF, nullptr, 0, 1, cent, up_W0, Wh, WhH);
    compute_s<<<NN / 8, 256>>>(Wh, up_a0, s1, s2);
    attn_kernel<<<attnGrid, attnBlk>>>(WhH2, s1, s2, cols, deg, p1, pi1, D1, bB, 1, nullptr);

    // unpool 1
    gemm_unpool<<<gemmGrid, 128>>>(bB, unpool_w1, unpool_b1, i0, bA);

    // up1 GAT (+D0 residual fused)
    gemm_cat<<<gemmGrid, 128>>>(bA, FF, nullptr, 0, 1, cent, up_W1, Wh, WhH);
    compute_s<<<NN / 8, 256>>>(Wh, up_a1, s1, s2);
    attn_kernel<<<attnGrid, attnBlk>>>(WhH2, s1, s2, cols, deg, idp, idp, D0, bB, 1, nullptr);

    // end GAT (concat fused into GEMM loader), no elu -> d_out
    gemm_cat<<<gemmGrid, 128>>>(bB, FF, org, FF, 1, cent, end_W, Wh, WhH);
    compute_s<<<NN / 8, 256>>>(Wh, end_a, s1, s2);
    attn_kernel<<<attnGrid, attnBlk>>>(WhH2, s1, s2, cols, deg, idp, idp, nullptr, outX, 0, nullptr);
}

// round 7
// speedup vs baseline: 2.1328x; 1.0133x over previous
#include <cuda_runtime.h>
#include <cuda_fp16.h>
#include <math.h>
#include <float.h>

#define NN 4096
#define FF 320
#define FH 160          // FF/2 (half2 columns)
#define MAXDEG 256
#define RPB 4           // rows per attn block
#define TPR 80          // threads per row (80 * uint2 = 320 floats)
#define NCB 5           // GEMM column blocks (FF/BN)

// ---------------- scratch (static __device__ globals; no allocations) ----------------
__device__ __half g_WhH[NN * FF];
__device__ float g_org[NN * FF];
__device__ float g_D0[NN * FF];
__device__ float g_D1[NN * FF];
__device__ float g_bA[NN * FF];
__device__ float g_bB[NN * FF];
__device__ float g_cent[NN];
__device__ float g_s1[NN];
__device__ float g_s2[NN];
__device__ float g_sp1[NCB * NN];
__device__ float g_sp2[NCB * NN];
__device__ float g_sc[NN];
__device__ int g_cols[NN * MAXDEG];
__device__ int g_deg[NN];
__device__ int g_idp[NN];
__device__ int g_p1[NN];
__device__ int g_p2[NN];
__device__ int g_pi1[NN];
__device__ int g_pi2[NN];
__device__ int g_i0[NN];
__device__ int g_i1[NN];

// ---------------- adjacency ELL build + degree centrality + identity perm (warp per row) ----------------
__global__ void build_adj(const float* __restrict__ A, int* __restrict__ cols,
                          int* __restrict__ deg, float* __restrict__ cent,
                          int* __restrict__ idp) {
    int warp = (blockIdx.x * blockDim.x + threadIdx.x) >> 5;
    int lane = threadIdx.x & 31;
    if (warp >= NN) return;
    long rowoff = (long)warp * NN;
    float sum = 0.f;
    int base = 0;
    for (int c0 = 0; c0 < NN; c0 += 32) {
        float v = A[rowoff + c0 + lane];
        sum += v;
        unsigned m = __ballot_sync(0xffffffffu, v > 0.f);
        if (v > 0.f) {
            int pos = base + __popc(m & ((1u << lane) - 1u));
            if (pos < MAXDEG) cols[(long)warp * MAXDEG + pos] = c0 + lane;
        }
        base += __popc(m);
    }
    for (int o = 16; o; o >>= 1) sum += __shfl_xor_sync(0xffffffffu, sum, o);
    if (lane == 0) {
        deg[warp] = base < MAXDEG ? base : MAXDEG;
        cent[warp] = sum / (float)(NN - 1);
        idp[warp] = warp;
    }
}

// ---------------- GEMM: CH(half) = [X1 | X2 | cent*nc] @ W ; fused s1/s2 partials ----------------
#define BM 64
#define BN 64
#define BK 16
#define BMP (BM + 4)

__global__ __launch_bounds__(128) void gemm_cat(
    const float* __restrict__ X1, int K1,
    const float* __restrict__ X2, int K2,
    int nc, const float* __restrict__ cent,
    const float* __restrict__ W, __half* __restrict__ CH,
    const float* __restrict__ av,     // attention vector (2*FF)
    float* __restrict__ sp1, float* __restrict__ sp2) {
    __shared__ float As[2][BK][BMP];
    __shared__ float Bs[2][BK][BN];
    int tid = threadIdx.x;
    int row0 = blockIdx.y * BM;
    int col0 = blockIdx.x * BN;
    int K12 = K1 + K2;
    int Ktot = K12 + nc;
    int nT = (Ktot + BK - 1) / BK;
    int tx = tid & 15, ty = tid >> 4;
    float acc[8][4];
#pragma unroll
    for (int i = 0; i < 8; i++)
#pragma unroll
        for (int j = 0; j < 4; j++) acc[i][j] = 0.f;

    int a_kk = tid & 15, a_m0 = tid >> 4;
    int b_n = tid & 63, b_kk0 = tid >> 6;

    {
        int k0 = 0;
#pragma unroll
        for (int l = 0; l < 8; l++) {
            int m = a_m0 + l * 8;
            int k = k0 + a_kk;
            int r = row0 + m;
            float v = 0.f;
            if (k < K1) v = X1[(long)r * K1 + k];
            else if (k < K12) v = X2[(long)r * K2 + (k - K1)];
            else if (k < Ktot) v = cent[r];
            As[0][a_kk][m] = v;
        }
#pragma unroll
        for (int l = 0; l < 8; l++) {
            int kk = b_kk0 + l * 2;
            int k = k0 + kk;
            Bs[0][kk][b_n] = (k < Ktot) ? W[(long)k * FF + col0 + b_n] : 0.f;
        }
    }
    __syncthreads();

    float pa[8], pb[8];
    for (int t = 0; t < nT; t++) {
        int buf = t & 1;
        bool hasNext = (t + 1 < nT);
        if (hasNext) {
            int k0 = (t + 1) * BK;
#pragma unroll
            for (int l = 0; l < 8; l++) {
                int m = a_m0 + l * 8;
                int k = k0 + a_kk;
                int r = row0 + m;
                float v = 0.f;
                if (k < K1) v = X1[(long)r * K1 + k];
                else if (k < K12) v = X2[(long)r * K2 + (k - K1)];
                else if (k < Ktot) v = cent[r];
                pa[l] = v;
            }
#pragma unroll
            for (int l = 0; l < 8; l++) {
                int kk = b_kk0 + l * 2;
                int k = k0 + kk;
                pb[l] = (k < Ktot) ? W[(long)k * FF + col0 + b_n] : 0.f;
            }
        }
#pragma unroll
        for (int kk = 0; kk < BK; kk++) {
            float4 a0 = *(const float4*)&As[buf][kk][ty * 8];
            float4 a1 = *(const float4*)&As[buf][kk][ty * 8 + 4];
            float4 b0 = *(const float4*)&Bs[buf][kk][tx * 4];
            float ra[8] = {a0.x, a0.y, a0.z, a0.w, a1.x, a1.y, a1.z, a1.w};
            float rb[4] = {b0.x, b0.y, b0.z, b0.w};
#pragma unroll
            for (int i = 0; i < 8; i++)
#pragma unroll
                for (int j = 0; j < 4; j++) acc[i][j] = fmaf(ra[i], rb[j], acc[i][j]);
        }
        if (hasNext) {
            int nbuf = 1 - buf;
#pragma unroll
            for (int l = 0; l < 8; l++) As[nbuf][a_kk][a_m0 + l * 8] = pa[l];
#pragma unroll
            for (int l = 0; l < 8; l++) Bs[nbuf][b_kk0 + l * 2][b_n] = pb[l];
            __syncthreads();
        }
    }
    // half output
#pragma unroll
    for (int i = 0; i < 8; i++) {
        int r = row0 + ty * 8 + i;
        long base = (long)r * FF + col0 + tx * 4;
        __half2* hdst = (__half2*)(CH + base);
        hdst[0] = __floats2half2_rn(acc[i][0], acc[i][1]);
        hdst[1] = __floats2half2_rn(acc[i][2], acc[i][3]);
    }
    // fused s1/s2 partials: p = sum_j acc[i][j] * a[col0+tx*4+j]
    float a1v[4], a2v[4];
#pragma unroll
    for (int j = 0; j < 4; j++) {
        int c = col0 + tx * 4 + j;
        a1v[j] = __ldg(av + c);
        a2v[j] = __ldg(av + FF + c);
    }
#pragma unroll
    for (int i = 0; i < 8; i++) {
        float p1 = acc[i][0] * a1v[0] + acc[i][1] * a1v[1] + acc[i][2] * a1v[2] + acc[i][3] * a1v[3];
        float p2 = acc[i][0] * a2v[0] + acc[i][1] * a2v[1] + acc[i][2] * a2v[2] + acc[i][3] * a2v[3];
#pragma unroll
        for (int o = 8; o; o >>= 1) {
            p1 += __shfl_down_sync(0xffffffffu, p1, o);
            p2 += __shfl_down_sync(0xffffffffu, p2, o);
        }
        if (tx == 0) {
            int r = row0 + ty * 8 + i;
            sp1[blockIdx.x * NN + r] = p1;
            sp2[blockIdx.x * NN + r] = p2;
        }
    }
}

// ---------------- finalize s1/s2: sum the 5 column-block partials ----------------
__global__ void finalize_s(const float* __restrict__ sp1, const float* __restrict__ sp2,
                           float* __restrict__ s1, float* __restrict__ s2) {
    int i = blockIdx.x * blockDim.x + threadIdx.x;
    if (i >= NN) return;
    float x1 = 0.f, x2 = 0.f;
#pragma unroll
    for (int b = 0; b < NCB; b++) {
        x1 += sp1[b * NN + i];
        x2 += sp2[b * NN + i];
    }
    s1[i] = x1;
    s2[i] = x2;
}

// ---------------- unpool: out[idx[i]][j] = X[i][j] * sigmoid((X @ W^T)[i][j] + b[j]) ----------------
#define BNP (BN + 4)
__global__ __launch_bounds__(128) void gemm_unpool(
    const float* __restrict__ X, const float* __restrict__ W,
    const float* __restrict__ b, const int* __restrict__ idxArr,
    float* __restrict__ out) {
    __shared__ float As[2][BK][BMP];
    __shared__ float Bs[2][BK][BNP];
    int tid = threadIdx.x;
    int row0 = blockIdx.y * BM;
    int col0 = blockIdx.x * BN;
    int tx = tid & 15, ty = tid >> 4;
    const int nT = FF / BK;   // 20
    float acc[8][4];
#pragma unroll
    for (int i = 0; i < 8; i++)
#pragma unroll
        for (int j = 0; j < 4; j++) acc[i][j] = 0.f;

    int a_kk = tid & 15, a_m0 = tid >> 4;
    int w_kk = tid & 15, w_n0 = tid >> 4;

    {
#pragma unroll
        for (int l = 0; l < 8; l++)
            As[0][a_kk][a_m0 + l * 8] = X[(long)(row0 + a_m0 + l * 8) * FF + a_kk];
#pragma unroll
        for (int l = 0; l < 8; l++)
            Bs[0][w_kk][w_n0 + l * 8] = W[(long)(col0 + w_n0 + l * 8) * FF + w_kk];
    }
    __syncthreads();

    float pa[8], pb[8];
    for (int t = 0; t < nT; t++) {
        int buf = t & 1;
        bool hasNext = (t + 1 < nT);
        if (hasNext) {
            int k0 = (t + 1) * BK;
#pragma unroll
            for (int l = 0; l < 8; l++)
                pa[l] = X[(long)(row0 + a_m0 + l * 8) * FF + k0 + a_kk];
#pragma unroll
            for (int l = 0; l < 8; l++)
                pb[l] = W[(long)(col0 + w_n0 + l * 8) * FF + k0 + w_kk];
        }
#pragma unroll
        for (int kk = 0; kk < BK; kk++) {
            float4 a0 = *(const float4*)&As[buf][kk][ty * 8];
            float4 a1 = *(const float4*)&As[buf][kk][ty * 8 + 4];
            float4 b0 = *(const float4*)&Bs[buf][kk][tx * 4];
            float ra[8] = {a0.x, a0.y, a0.z, a0.w, a1.x, a1.y, a1.z, a1.w};
            float rb[4] = {b0.x, b0.y, b0.z, b0.w};
#pragma unroll
            for (int i = 0; i < 8; i++)
#pragma unroll
                for (int j = 0; j < 4; j++) acc[i][j] = fmaf(ra[i], rb[j], acc[i][j]);
        }
        if (hasNext) {
            int nbuf = 1 - buf;
#pragma unroll
            for (int l = 0; l < 8; l++) As[nbuf][a_kk][a_m0 + l * 8] = pa[l];
#pragma unroll
            for (int l = 0; l < 8; l++) Bs[nbuf][w_kk][w_n0 + l * 8] = pb[l];
            __syncthreads();
        }
    }
#pragma unroll
    for (int i = 0; i < 8; i++) {
        int r = row0 + ty * 8 + i;
        int dst = idxArr[r];
#pragma unroll
        for (int j = 0; j < 4; j++) {
            int c = col0 + tx * 4 + j;
            float aw = 1.f / (1.f + expf(-(acc[i][j] + b[c])));
            out[(long)dst * FF + c] = X[(long)r * FF + c] * aw;
        }
    }
}

// ---------------- pool scores: sigmoid((X@w + b)/100) (warp per row) ----------------
__global__ void scores_k(const float* __restrict__ X, const float* __restrict__ w,
                         const float* __restrict__ b, float* __restrict__ sc) {
    int warp = (blockIdx.x * blockDim.x + threadIdx.x) >> 5;
    int lane = threadIdx.x & 31;
    if (warp >= NN) return;
    const float* row = X + (long)warp * FF;
    float z = 0.f;
#pragma unroll
    for (int it = 0; it < 10; it++) {
        int t = lane + it * 32;
        z = fmaf(__ldg(row + t), __ldg(w + t), z);
    }
    for (int o = 16; o; o >>= 1) z += __shfl_down_sync(0xffffffffu, z, o);
    if (lane == 0) {
        float v = (z + b[0]) * 0.01f;
        sc[warp] = 1.f / (1.f + expf(-v));
    }
}

// ---------------- stable descending rank (top_k with k=N semantics) ----------------
__global__ void rank_kernel(const float* __restrict__ s, int* __restrict__ idxArr) {
    __shared__ int red[256];
    int i = blockIdx.x;
    int tid = threadIdx.x;
    float si = s[i];
    int cnt = 0;
    for (int j = tid; j < NN; j += 256) {
        float sj = s[j];
        cnt += (sj > si) || (sj == si && j < i);
    }
    red[tid] = cnt;
    __syncthreads();
    for (int st = 128; st > 0; st >>= 1) {
        if (tid < st) red[tid] += red[tid + st];
        __syncthreads();
    }
    if (tid == 0) idxArr[red[0]] = i;
}

// ---------------- apply pool: permute X*value, update perm + inverse ----------------
__global__ void pool_apply(const float* __restrict__ Xold, const float* __restrict__ sc,
                           const int* __restrict__ idxArr, const int* __restrict__ pOld,
                           int* __restrict__ pNew, int* __restrict__ pinvNew,
                           float* __restrict__ Xnew) {
    int r = blockIdx.x;
    int o = idxArr[r];
    if (threadIdx.x == 0) {
        int po = pOld[o];
        pNew[r] = po;
        pinvNew[po] = r;
    }
    float v = sc[o];
    int t = threadIdx.x;
    Xnew[(long)r * FF + t] = Xold[(long)o * FF + t] * v;
}

// ---------------- sparse GAT attention: 4 rows/block, 80 threads/row, uint2 gathers ----------------
__global__ __launch_bounds__(RPB * TPR) void attn_kernel(
    const __half2* __restrict__ WhH, const float* __restrict__ s1,
    const float* __restrict__ s2, const int* __restrict__ cols,
    const int* __restrict__ deg, const int* __restrict__ p,
    const int* __restrict__ pinv, const float* __restrict__ resid,
    float* __restrict__ out, int applyElu, float* __restrict__ out2) {
    __shared__ float2 pk[RPB][MAXDEG];   // .x = byte offset (int bits), .y = score
    __shared__ float red[RPB][TPR];
    int tid = threadIdx.x;
    int r = tid / TPR, t = tid - r * TPR;
    int i = blockIdx.x * RPB + r;
    int orig = p[i];
    int d = deg[orig];
    float si = s1[i];
    // fill neighbor workspace; WhH row stride = FH half2 = FH*4 bytes
    for (int k = t; k < d; k += TPR) {
        int c = __ldg(cols + (long)orig * MAXDEG + k);
        int rr = __ldg(pinv + c);
        float e = si + __ldg(s2 + rr);
        e = e > 0.f ? e : 0.2f * e;   // leaky_relu(0.2)
        pk[r][k] = make_float2(__int_as_float(rr * (FH * 4)), e);
    }
    __syncthreads();
    // max reduce
    float m = -FLT_MAX;
    for (int k = t; k < d; k += TPR) m = fmaxf(m, pk[r][k].y);
    red[r][t] = m;
    __syncthreads();
#pragma unroll
    for (int s = 64; s > 0; s >>= 1) {
        if (t < s && t + s < TPR) red[r][t] = fmaxf(red[r][t], red[r][t + s]);
        __syncthreads();
    }
    m = red[r][0];
    __syncthreads();
    // exp & sum
    float ssum = 0.f;
    for (int k = t; k < d; k += TPR) {
        float e = __expf(pk[r][k].y - m);
        pk[r][k].y = e;
        ssum += e;
    }
    red[r][t] = ssum;
    __syncthreads();
#pragma unroll
    for (int s = 64; s > 0; s >>= 1) {
        if (t < s && t + s < TPR) red[r][t] += red[r][t + s];
        __syncthreads();
    }
    float inv = 1.f / red[r][0];
    // aggregation: thread t covers half2 columns 2t, 2t+1 (floats 4t..4t+3)
    const char* basep = (const char*)WhH + t * 8;
    float acc[2][4];
#pragma unroll
    for (int u = 0; u < 2; u++)
#pragma unroll
        for (int c = 0; c < 4; c++) acc[u][c] = 0.f;
    int d8 = d & ~7;
    int k = 0;
    for (; k < d8; k += 8) {
        float2 pe[8];
        uint2 v[8];
#pragma unroll
        for (int u = 0; u < 8; u++) pe[u] = pk[r][k + u];
#pragma unroll
        for (int u = 0; u < 8; u++)
            v[u] = __ldg((const uint2*)(basep + __float_as_int(pe[u].x)));
#pragma unroll
        for (int u = 0; u < 8; u++) {
            float2 f0 = __half22float2(*(const __half2*)&v[u].x);
            float2 f1 = __half22float2(*(const __half2*)&v[u].y);
            int s = u & 1;
            float e = pe[u].y;
            acc[s][0] = fmaf(e, f0.x, acc[s][0]);
            acc[s][1] = fmaf(e, f0.y, acc[s][1]);
            acc[s][2] = fmaf(e, f1.x, acc[s][2]);
            acc[s][3] = fmaf(e, f1.y, acc[s][3]);
        }
    }
    for (; k < d; k++) {
        float2 pe = pk[r][k];
        uint2 v = __ldg((const uint2*)(basep + __float_as_int(pe.x)));
        float2 f0 = __half22float2(*(const __half2*)&v.x);
        float2 f1 = __half22float2(*(const __half2*)&v.y);
        float e = pe.y;
        acc[0][0] = fmaf(e, f0.x, acc[0][0]);
        acc[0][1] = fmaf(e, f0.y, acc[0][1]);
        acc[0][2] = fmaf(e, f1.x, acc[0][2]);
        acc[0][3] = fmaf(e, f1.y, acc[0][3]);
    }
    float4 o4;
    o4.x = (acc[0][0] + acc[1][0]) * inv;
    o4.y = (acc[0][1] + acc[1][1]) * inv;
    o4.z = (acc[0][2] + acc[1][2]) * inv;
    o4.w = (acc[0][3] + acc[1][3]) * inv;
    if (applyElu) {
        o4.x = o4.x > 0.f ? o4.x : expm1f(o4.x);
        o4.y = o4.y > 0.f ? o4.y : expm1f(o4.y);
        o4.z = o4.z > 0.f ? o4.z : expm1f(o4.z);
        o4.w = o4.w > 0.f ? o4.w : expm1f(o4.w);
    }
    long base = (long)i * FF + 4 * t;
    if (resid) {
        float4 rv = *(const float4*)(resid + base);
        o4.x += rv.x; o4.y += rv.y; o4.z += rv.z; o4.w += rv.w;
    }
    *(float4*)(out + base) = o4;
    if (out2) *(float4*)(out2 + base) = o4;
}

// ---------------- host driver ----------------
static void* sym(const void* s) {
    void* p = nullptr;
    cudaGetSymbolAddress(&p, s);
    return p;
}

extern "C" void kernel_launch(void* const* d_in, const int* in_sizes, int n_in,
                              void* d_out, int out_size) {
    const float* A        = (const float*)d_in[0];
    const float* X        = (const float*)d_in[1];
    const float* start_W  = (const float*)d_in[2];
    const float* start_a  = (const float*)d_in[3];
    const float* bottom_W = (const float*)d_in[4];
    const float* bottom_a = (const float*)d_in[5];
    const float* end_W    = (const float*)d_in[6];
    const float* end_a    = (const float*)d_in[7];
    const float* down_W0  = (const float*)d_in[8];
    const float* down_a0  = (const float*)d_in[9];
    const float* up_W0    = (const float*)d_in[10];
    const float* up_a0    = (const float*)d_in[11];
    const float* pool_w0  = (const float*)d_in[12];
    const float* pool_b0  = (const float*)d_in[13];
    const float* unpool_w0= (const float*)d_in[14];
    const float* unpool_b0= (const float*)d_in[15];
    const float* down_W1  = (const float*)d_in[16];
    const float* down_a1  = (const float*)d_in[17];
    const float* up_W1    = (const float*)d_in[18];
    const float* up_a1    = (const float*)d_in[19];
    const float* pool_w1  = (const float*)d_in[20];
    const float* pool_b1  = (const float*)d_in[21];
    const float* unpool_w1= (const float*)d_in[22];
    const float* unpool_b1= (const float*)d_in[23];

    __half* WhH  = (__half*)sym(g_WhH);
    float* org   = (float*)sym(g_org);
    float* D0    = (float*)sym(g_D0);
    float* D1    = (float*)sym(g_D1);
    float* bA    = (float*)sym(g_bA);
    float* bB    = (float*)sym(g_bB);
    float* cent  = (float*)sym(g_cent);
    float* s1    = (float*)sym(g_s1);
    float* s2    = (float*)sym(g_s2);
    float* sp1   = (float*)sym(g_sp1);
    float* sp2   = (float*)sym(g_sp2);
    float* sc    = (float*)sym(g_sc);
    int* cols = (int*)sym(g_cols);
    int* deg  = (int*)sym(g_deg);
    int* idp  = (int*)sym(g_idp);
    int* p1   = (int*)sym(g_p1);
    int* p2   = (int*)sym(g_p2);
    int* pi1  = (int*)sym(g_pi1);
    int* pi2  = (int*)sym(g_pi2);
    int* i0   = (int*)sym(g_i0);
    int* i1   = (int*)sym(g_i1);

    float* outX = (float*)d_out;
    float* out2 = outX + (long)NN * FF;   // second output = start_out
    const __half2* WhH2 = (const __half2*)WhH;

    dim3 gemmGrid(FF / BN, NN / BM);   // (5, 64) = 320 blocks
    int attnGrid = NN / RPB;           // 1024
    int attnBlk = RPB * TPR;           // 320

    build_adj<<<NN / 8, 256>>>(A, cols, deg, cent, idp);

    // start GAT
    gemm_cat<<<gemmGrid, 128>>>(X, FF, nullptr, 0, 2, cent, start_W, WhH, start_a, sp1, sp2);
    finalize_s<<<NN / 256, 256>>>(sp1, sp2, s1, s2);
    attn_kernel<<<attnGrid, attnBlk>>>(WhH2, s1, s2, cols, deg, idp, idp, nullptr, org, 1, out2);

    // down0 GAT
    gemm_cat<<<gemmGrid, 128>>>(org, FF, nullptr, 0, 1, cent, down_W0, WhH, down_a0, sp1, sp2);
    finalize_s<<<NN / 256, 256>>>(sp1, sp2, s1, s2);
    attn_kernel<<<attnGrid, attnBlk>>>(WhH2, s1, s2, cols, deg, idp, idp, nullptr, D0, 1, nullptr);

    // pool 0
    scores_k<<<NN / 8, 256>>>(D0, pool_w0, pool_b0, sc);
    rank_kernel<<<NN, 256>>>(sc, i0);
    pool_apply<<<NN, 320>>>(D0, sc, i0, idp, p1, pi1, bA);

    // down1 GAT
    gemm_cat<<<gemmGrid, 128>>>(bA, FF, nullptr, 0, 1, cent, down_W1, WhH, down_a1, sp1, sp2);
    finalize_s<<<NN / 256, 256>>>(sp1, sp2, s1, s2);
    attn_kernel<<<attnGrid, attnBlk>>>(WhH2, s1, s2, cols, deg, p1, pi1, nullptr, D1, 1, nullptr);

    // pool 1
    scores_k<<<NN / 8, 256>>>(D1, pool_w1, pool_b1, sc);
    rank_kernel<<<NN, 256>>>(sc, i1);
    pool_apply<<<NN, 320>>>(D1, sc, i1, p1, p2, pi2, bA);

    // bottom GAT
    gemm_cat<<<gemmGrid, 128>>>(bA, FF, nullptr, 0, 1, cent, bottom_W, WhH, bottom_a, sp1, sp2);
    finalize_s<<<NN / 256, 256>>>(sp1, sp2, s1, s2);
    attn_kernel<<<attnGrid, attnBlk>>>(WhH2, s1, s2, cols, deg, p2, pi2, nullptr, bB, 1, nullptr);

    // unpool 0
    gemm_unpool<<<gemmGrid, 128>>>(bB, unpool_w0, unpool_b0, i1, bA);

    // up0 GAT (+D1 residual fused)
    gemm_cat<<<gemmGrid, 128>>>(bA, FF, nullptr, 0, 1, cent, up_W0, WhH, up_a0, sp1, sp2);
    finalize_s<<<NN / 256, 256>>>(sp1, sp2, s1, s2);
    attn_kernel<<<attnGrid, attnBlk>>>(WhH2, s1, s2, cols, deg, p1, pi1, D1, bB, 1, nullptr);

    // unpool 1
    gemm_unpool<<<gemmGrid, 128>>>(bB, unpool_w1, unpool_b1, i0, bA);

    // up1 GAT (+D0 residual fused)
    gemm_cat<<<gemmGrid, 128>>>(bA, FF, nullptr, 0, 1, cent, up_W1, WhH, up_a1, sp1, sp2);
    finalize_s<<<NN / 256, 256>>>(sp1, sp2, s1, s2);
    attn_kernel<<<attnGrid, attnBlk>>>(WhH2, s1, s2, cols, deg, idp, idp, D0, bB, 1, nullptr);

    // end GAT (concat fused into GEMM loader), no elu -> d_out
    gemm_cat<<<gemmGrid, 128>>>(bB, FF, org, FF, 1, cent, end_W, WhH, end_a, sp1, sp2);
    finalize_s<<<NN / 256, 256>>>(sp1, sp2, s1, s2);
    attn_kernel<<<attnGrid, attnBlk>>>(WhH2, s1, s2, cols, deg, idp, idp, nullptr, outX, 0, nullptr);
}